// round 1
// baseline (speedup 1.0000x reference)
#include <cuda_runtime.h>
#include <math.h>

// Problem constants
#define Bv 2
#define Tv 2048
#define Dv 1024
#define Hv 16
#define HDv 64
#define Mv (Bv*Tv)      // 4096 rows
#define WINDOWv 10

// ---------------------------------------------------------------------------
// Scratch (static __device__ arrays; no allocation allowed)
// ---------------------------------------------------------------------------
__device__ float g_h  [Mv * Dv];        // LN output (reused for LN1 and LN2)
__device__ float g_qkv[Mv * 3 * Dv];    // QKV projection output
__device__ float g_o  [Mv * Dv];        // attention output (pre out-proj)
__device__ float g_ff [Mv * 4 * Dv];    // FFN hidden

// ---------------------------------------------------------------------------
// LayerNorm: one block per row (D=1024), 256 threads, 4 elems/thread
// ---------------------------------------------------------------------------
__global__ void ln_kernel(const float* __restrict__ x, const float* __restrict__ g,
                          const float* __restrict__ beta, float* __restrict__ out)
{
    int row = blockIdx.x;
    int tid = threadIdx.x;
    const float4* xr = (const float4*)(x + (size_t)row * Dv);
    float4 v = xr[tid];
    float s  = v.x + v.y + v.z + v.w;
    float sq = v.x*v.x + v.y*v.y + v.z*v.z + v.w*v.w;
    #pragma unroll
    for (int o = 16; o > 0; o >>= 1) {
        s  += __shfl_xor_sync(0xffffffffu, s, o);
        sq += __shfl_xor_sync(0xffffffffu, sq, o);
    }
    __shared__ float rs[8], rq[8];
    __shared__ float smean, srstd;
    int w = tid >> 5;
    if ((tid & 31) == 0) { rs[w] = s; rq[w] = sq; }
    __syncthreads();
    if (tid == 0) {
        float ts = 0.f, tq = 0.f;
        #pragma unroll
        for (int i = 0; i < 8; i++) { ts += rs[i]; tq += rq[i]; }
        float mean = ts * (1.0f / Dv);
        float var  = tq * (1.0f / Dv) - mean * mean;
        smean = mean;
        srstd = rsqrtf(var + 1e-5f);
    }
    __syncthreads();
    float mean = smean, rstd = srstd;
    float4 gg = ((const float4*)g)[tid];
    float4 bb = ((const float4*)beta)[tid];
    float4 o4;
    o4.x = (v.x - mean) * rstd * gg.x + bb.x;
    o4.y = (v.y - mean) * rstd * gg.y + bb.y;
    o4.z = (v.z - mean) * rstd * gg.z + bb.z;
    o4.w = (v.w - mean) * rstd * gg.w + bb.w;
    ((float4*)(out + (size_t)row * Dv))[tid] = o4;
}

// ---------------------------------------------------------------------------
// SGEMM (NT): C[M,N] = A[M,K] * W[N,K]^T + bias (+ epilogue)
//   EPI 0: bias only
//   EPI 1: bias + exact-erf GELU
//   EPI 2: bias + residual add (res may alias C; same-element read-before-write)
// 128x128x16 tiles, 256 threads, 8x8 per-thread micro-tile.
// ---------------------------------------------------------------------------
__device__ __forceinline__ float gelu_exact(float x) {
    return 0.5f * x * (1.0f + erff(x * 0.70710678118654752f));
}

template<int EPI>
__global__ __launch_bounds__(256, 2) void sgemm_nt(
    const float* __restrict__ A, const float* __restrict__ W,
    const float* __restrict__ bias, const float* __restrict__ res,
    float* __restrict__ C, int M, int N, int K)
{
    __shared__ float As[16][128];
    __shared__ float Bs[16][128];

    int tid = threadIdx.x;
    int m0 = blockIdx.y * 128;
    int n0 = blockIdx.x * 128;

    float acc[8][8];
    #pragma unroll
    for (int i = 0; i < 8; i++)
        #pragma unroll
        for (int j = 0; j < 8; j++) acc[i][j] = 0.f;

    int lrow = tid >> 2;            // 0..63
    int lc4  = (tid & 3) << 2;      // 0,4,8,12
    const float* Aptr = A + (size_t)(m0 + lrow) * K + lc4;
    const float* Wptr = W + (size_t)(n0 + lrow) * K + lc4;

    int am = (tid >> 4) << 3;       // 0..120 step 8 (row frag)
    int bn = (tid & 15) << 3;       // col frag

    for (int k0 = 0; k0 < K; k0 += 16) {
        float4 a0 = *(const float4*)(Aptr + k0);
        float4 a1 = *(const float4*)(Aptr + (size_t)64 * K + k0);
        float4 b0 = *(const float4*)(Wptr + k0);
        float4 b1 = *(const float4*)(Wptr + (size_t)64 * K + k0);
        __syncthreads();
        As[lc4+0][lrow] = a0.x; As[lc4+1][lrow] = a0.y; As[lc4+2][lrow] = a0.z; As[lc4+3][lrow] = a0.w;
        As[lc4+0][lrow+64] = a1.x; As[lc4+1][lrow+64] = a1.y; As[lc4+2][lrow+64] = a1.z; As[lc4+3][lrow+64] = a1.w;
        Bs[lc4+0][lrow] = b0.x; Bs[lc4+1][lrow] = b0.y; Bs[lc4+2][lrow] = b0.z; Bs[lc4+3][lrow] = b0.w;
        Bs[lc4+0][lrow+64] = b1.x; Bs[lc4+1][lrow+64] = b1.y; Bs[lc4+2][lrow+64] = b1.z; Bs[lc4+3][lrow+64] = b1.w;
        __syncthreads();

        #pragma unroll
        for (int kk = 0; kk < 16; kk++) {
            float a[8], b[8];
            *(float4*)&a[0] = *(const float4*)&As[kk][am];
            *(float4*)&a[4] = *(const float4*)&As[kk][am + 4];
            *(float4*)&b[0] = *(const float4*)&Bs[kk][bn];
            *(float4*)&b[4] = *(const float4*)&Bs[kk][bn + 4];
            #pragma unroll
            for (int i = 0; i < 8; i++)
                #pragma unroll
                for (int j = 0; j < 8; j++)
                    acc[i][j] += a[i] * b[j];
        }
    }

    int r0 = m0 + am;
    int c0 = n0 + bn;
    float bb[8];
    *(float4*)&bb[0] = *(const float4*)&bias[c0];
    *(float4*)&bb[4] = *(const float4*)&bias[c0 + 4];

    #pragma unroll
    for (int i = 0; i < 8; i++) {
        #pragma unroll
        for (int j = 0; j < 8; j += 4) {
            float4 v;
            v.x = acc[i][j+0] + bb[j+0];
            v.y = acc[i][j+1] + bb[j+1];
            v.z = acc[i][j+2] + bb[j+2];
            v.w = acc[i][j+3] + bb[j+3];
            if (EPI == 1) {
                v.x = gelu_exact(v.x); v.y = gelu_exact(v.y);
                v.z = gelu_exact(v.z); v.w = gelu_exact(v.w);
            }
            if (EPI == 2) {
                float4 rr = *(const float4*)&res[(size_t)(r0 + i) * N + c0 + j];
                v.x += rr.x; v.y += rr.y; v.z += rr.z; v.w += rr.w;
            }
            *(float4*)&C[(size_t)(r0 + i) * N + c0 + j] = v;
        }
    }
}

// ---------------------------------------------------------------------------
// Flash-style banded attention.
// CTA = (q-tile of 64, head, batch); 256 threads = 8 warps; warp owns 8 query
// rows. Key tiles of 64 processed with online softmax.
// Smem (dynamic, 64 KB): Qs[64][64] (pre-scaled by 1/8 * log2(e)),
// Kst[64 d][64 j] (d-major -> within-row reads, conflict-free),
// Vs[64 j][64 d], Ps[64 r][64 j]. All reads are broadcast or within-row.
// ---------------------------------------------------------------------------
__global__ void attn_kernel(const float* __restrict__ qkv, float* __restrict__ o)
{
    extern __shared__ float smem[];
    float* Qs  = smem;
    float* Kst = smem + 4096;
    float* Vs  = smem + 8192;
    float* Ps  = smem + 12288;

    int tid  = threadIdx.x;
    int lane = tid & 31;
    int w    = tid >> 5;
    int q0   = blockIdx.x * 64;
    int h    = blockIdx.y;
    int b    = blockIdx.z;

    const float SCALE = 0.125f * 1.4426950408889634f;  // 1/sqrt(64) * log2(e)

    // Load + pre-scale Q tile
    for (int i = tid; i < 64 * 16; i += 256) {
        int row = i >> 4;
        int c4  = (i & 15) << 2;
        float4 q = *(const float4*)&qkv[(size_t)(b * Tv + q0 + row) * 3072 + h * 64 + c4];
        float* dst = &Qs[row * 64 + c4];
        dst[0] = q.x * SCALE; dst[1] = q.y * SCALE;
        dst[2] = q.z * SCALE; dst[3] = q.w * SCALE;
    }

    float s[8][2], oacc[8][2], mrow[8], lrow[8];
    #pragma unroll
    for (int r = 0; r < 8; r++) {
        oacc[r][0] = 0.f; oacc[r][1] = 0.f;
        mrow[r] = -1e30f; lrow[r] = 0.f;
    }

    int kmax   = min(q0 + 64 + WINDOWv, Tv);   // exclusive max key index
    int ntiles = (kmax + 63) >> 6;

    for (int kt = 0; kt < ntiles; kt++) {
        int k0 = kt << 6;
        __syncthreads();
        // Load K (transposed to d-major) and V tiles
        for (int i = tid; i < 64 * 16; i += 256) {
            int row = i >> 4;
            int c4  = (i & 15) << 2;
            const float* base = &qkv[(size_t)(b * Tv + k0 + row) * 3072 + h * 64 + c4];
            float4 kk = *(const float4*)(base + 1024);
            Kst[(c4+0)*64 + row] = kk.x;
            Kst[(c4+1)*64 + row] = kk.y;
            Kst[(c4+2)*64 + row] = kk.z;
            Kst[(c4+3)*64 + row] = kk.w;
            float4 vv = *(const float4*)(base + 2048);
            *(float4*)&Vs[row * 64 + c4] = vv;
        }
        __syncthreads();

        #pragma unroll
        for (int r = 0; r < 8; r++) { s[r][0] = 0.f; s[r][1] = 0.f; }

        // S = Q K^T (log2 domain). Lane owns keys j0=k0+2*lane, j0+1.
        #pragma unroll 8
        for (int d = 0; d < 64; d += 2) {
            float2 ka = *(float2*)&Kst[d * 64 + 2 * lane];
            float2 kb = *(float2*)&Kst[(d + 1) * 64 + 2 * lane];
            #pragma unroll
            for (int r = 0; r < 8; r++) {
                float2 q = *(float2*)&Qs[(w * 8 + r) * 64 + d];
                s[r][0] += q.x * ka.x + q.y * kb.x;
                s[r][1] += q.x * ka.y + q.y * kb.y;
            }
        }

        // Mask + online softmax update (per warp row)
        int j0 = k0 + 2 * lane;
        #pragma unroll
        for (int r = 0; r < 8; r++) {
            int iq = q0 + w * 8 + r;
            float s0 = (j0     <= iq + WINDOWv) ? s[r][0] : -1e30f;
            float s1 = (j0 + 1 <= iq + WINDOWv) ? s[r][1] : -1e30f;
            float mx = fmaxf(s0, s1);
            #pragma unroll
            for (int off = 16; off > 0; off >>= 1)
                mx = fmaxf(mx, __shfl_xor_sync(0xffffffffu, mx, off));
            float mnew = fmaxf(mrow[r], mx);
            float corr = exp2f(mrow[r] - mnew);
            float p0 = exp2f(s0 - mnew);
            float p1 = exp2f(s1 - mnew);
            float ps = p0 + p1;
            #pragma unroll
            for (int off = 16; off > 0; off >>= 1)
                ps += __shfl_xor_sync(0xffffffffu, ps, off);
            lrow[r] = lrow[r] * corr + ps;
            oacc[r][0] *= corr;
            oacc[r][1] *= corr;
            mrow[r] = mnew;
            *(float2*)&Ps[(w * 8 + r) * 64 + 2 * lane] = make_float2(p0, p1);
        }
        __syncwarp();

        // O += P V. Lane owns hd dims d0=2*lane, d0+1. P reads are broadcast.
        #pragma unroll 8
        for (int j = 0; j < 64; j += 2) {
            float2 va = *(float2*)&Vs[j * 64 + 2 * lane];
            float2 vb = *(float2*)&Vs[(j + 1) * 64 + 2 * lane];
            #pragma unroll
            for (int r = 0; r < 8; r++) {
                float2 p = *(float2*)&Ps[(w * 8 + r) * 64 + j];
                oacc[r][0] += p.x * va.x + p.y * vb.x;
                oacc[r][1] += p.x * va.y + p.y * vb.y;
            }
        }
        __syncwarp();
    }

    // Normalize and write out in [B,T,H*HD] layout
    #pragma unroll
    for (int r = 0; r < 8; r++) {
        float inv = 1.0f / lrow[r];
        float2 ov = make_float2(oacc[r][0] * inv, oacc[r][1] * inv);
        *(float2*)&o[(size_t)(b * Tv + q0 + w * 8 + r) * Dv + h * 64 + 2 * lane] = ov;
    }
}

// ---------------------------------------------------------------------------
// Launch
// ---------------------------------------------------------------------------
extern "C" void kernel_launch(void* const* d_in, const int* in_sizes, int n_in,
                              void* d_out, int out_size)
{
    const float* x     = (const float*)d_in[0];
    const float* in_w  = (const float*)d_in[1];
    const float* in_b  = (const float*)d_in[2];
    const float* out_w = (const float*)d_in[3];
    const float* out_b = (const float*)d_in[4];
    const float* ln1g  = (const float*)d_in[5];
    const float* ln1b  = (const float*)d_in[6];
    const float* w1    = (const float*)d_in[7];
    const float* b1    = (const float*)d_in[8];
    const float* w2    = (const float*)d_in[9];
    const float* b2    = (const float*)d_in[10];
    const float* ln2g  = (const float*)d_in[11];
    const float* ln2b  = (const float*)d_in[12];
    float* out = (float*)d_out;

    float *h, *qkv, *o, *ff;
    cudaGetSymbolAddress((void**)&h,   g_h);
    cudaGetSymbolAddress((void**)&qkv, g_qkv);
    cudaGetSymbolAddress((void**)&o,   g_o);
    cudaGetSymbolAddress((void**)&ff,  g_ff);

    // Attention kernel needs 64 KB dynamic smem (idempotent; first call is
    // outside graph capture, so the attribute is set before capture).
    cudaFuncSetAttribute(attn_kernel, cudaFuncAttributeMaxDynamicSharedMemorySize, 64 * 1024);

    // 1) h = LN1(x)
    ln_kernel<<<Mv, 256>>>(x, ln1g, ln1b, h);

    // 2) qkv = h @ in_proj_w^T + in_proj_b        [4096, 3072]
    sgemm_nt<0><<<dim3(3072 / 128, Mv / 128), 256>>>(h, in_w, in_b, nullptr, qkv, Mv, 3072, 1024);

    // 3) o = banded_flash_attention(qkv)          [4096, 1024]
    attn_kernel<<<dim3(Tv / 64, Hv, Bv), 256, 64 * 1024>>>(qkv, o);

    // 4) x1 = o @ out_w^T + out_b + x  -> d_out
    sgemm_nt<2><<<dim3(1024 / 128, Mv / 128), 256>>>(o, out_w, out_b, x, out, Mv, 1024, 1024);

    // 5) h2 = LN2(x1)
    ln_kernel<<<Mv, 256>>>(out, ln2g, ln2b, h);

    // 6) ff = GELU(h2 @ w1^T + b1)                [4096, 4096]
    sgemm_nt<1><<<dim3(4096 / 128, Mv / 128), 256>>>(h, w1, b1, nullptr, ff, Mv, 4096, 1024);

    // 7) out = ff @ w2^T + b2 + x1  (in-place residual on d_out)
    sgemm_nt<2><<<dim3(1024 / 128, Mv / 128), 256>>>(ff, w2, b2, out, out, Mv, 1024, 4096);
}

// round 3
// speedup vs baseline: 2.0074x; 2.0074x over previous
#include <cuda_runtime.h>
#include <math.h>
#include <cstdint>

// Problem constants
#define Bv 2
#define Tv 2048
#define Dv 1024
#define Hv 16
#define Mv 4096          // B*T
#define WINDOWv 10

// ---------------------------------------------------------------------------
// Scratch (static __device__ arrays; no allocation allowed)
// ---------------------------------------------------------------------------
__device__ float g_h  [Mv * Dv];          // LN output (tf32-rounded)
__device__ float g_qkv[Mv * 3 * Dv];      // QKV projection output
__device__ float g_o  [Mv * Dv];          // attention output (tf32-rounded)
__device__ float g_ff [Mv * 4 * Dv];      // FFN hidden (tf32-rounded)
__device__ float g_wqkv[3 * Dv * Dv];     // tf32-rounded weights
__device__ float g_wout[Dv * Dv];
__device__ float g_w1r [4 * Dv * Dv];
__device__ float g_w2r [Dv * 4 * Dv];

// ---------------------------------------------------------------------------
// Helpers
// ---------------------------------------------------------------------------
__device__ __forceinline__ float tf32r(float x) {
    uint32_t r;
    asm("cvt.rna.tf32.f32 %0, %1;" : "=r"(r) : "f"(x));
    return __uint_as_float(r);
}

__device__ __forceinline__ void cp16(void* dst, const void* src) {
    uint32_t d;
    asm("{ .reg .u64 t; cvta.to.shared.u64 t, %1; cvt.u32.u64 %0, t; }" : "=r"(d) : "l"(dst));
    asm volatile("cp.async.cg.shared.global [%0], [%1], 16;" :: "r"(d), "l"(src) : "memory");
}

__device__ __forceinline__ float gelu_exact(float x) {
    return 0.5f * x * (1.0f + erff(x * 0.70710678118654752f));
}

// m16n8k8 tf32 mma, fp32 accumulate
__device__ __forceinline__ void mma_tf32(float* c, const uint32_t* a, const uint32_t* b) {
    asm volatile(
        "mma.sync.aligned.m16n8k8.row.col.f32.tf32.tf32.f32 "
        "{%0,%1,%2,%3}, {%4,%5,%6,%7}, {%8,%9}, {%0,%1,%2,%3};"
        : "+f"(c[0]), "+f"(c[1]), "+f"(c[2]), "+f"(c[3])
        : "r"(a[0]), "r"(a[1]), "r"(a[2]), "r"(a[3]), "r"(b[0]), "r"(b[1]));
}

// ---------------------------------------------------------------------------
// Weight tf32-rounding prep
// ---------------------------------------------------------------------------
__global__ void round_w_kernel(const float4* __restrict__ in, float4* __restrict__ out, int n4) {
    int i = blockIdx.x * blockDim.x + threadIdx.x;
    int stride = gridDim.x * blockDim.x;
    for (; i < n4; i += stride) {
        float4 v = in[i];
        v.x = tf32r(v.x); v.y = tf32r(v.y); v.z = tf32r(v.z); v.w = tf32r(v.w);
        out[i] = v;
    }
}

// ---------------------------------------------------------------------------
// tf32 mma.sync GEMM: C[M,N] = A[M,K] * W[N,K]^T + bias (+ epilogue)
//   EPI 0: bias   EPI 1: bias + GELU (tf32-rounded)   EPI 2: bias + residual
// CTA tile 128x128, BK=32, 8 warps (4 along M x 2 along N), warp tile 32x64.
// Smem rows padded to 36 floats: fragment LDS bank = (4r+c)%32, conflict-free.
// 3-stage cp.async pipeline.
// ---------------------------------------------------------------------------
#define BM 128
#define BN 128
#define BK 32
#define GSTAGES 3
#define ROWF 36                       // padded row length in floats
#define STAGEF (128 * ROWF)           // floats per (A or B) stage
#define SMEM_FLOATS (2 * GSTAGES * STAGEF)   // 27648 floats = 110592 B

template<int EPI>
__device__ __forceinline__ void gemm_load_stage(float* smemf, int slot, int kt,
                                                const float* __restrict__ A,
                                                const float* __restrict__ W,
                                                int m0, int n0, int K, int tid)
{
    float* As = smemf + slot * STAGEF;
    float* Bs = smemf + (GSTAGES + slot) * STAGEF;
    int k0 = kt * BK;
    const float* Ag = A + (size_t)m0 * K + k0;
    const float* Wg = W + (size_t)n0 * K + k0;
    // 128 rows x 32 floats = 1024 x float4 chunks; 256 threads -> 4 each
    #pragma unroll
    for (int i = 0; i < 4; i++) {
        int idx = tid + i * 256;
        int r = idx >> 3, c = (idx & 7) << 2;   // c in floats
        cp16(As + r * ROWF + c, Ag + (size_t)r * K + c);
    }
    #pragma unroll
    for (int i = 0; i < 4; i++) {
        int idx = tid + i * 256;
        int r = idx >> 3, c = (idx & 7) << 2;
        cp16(Bs + r * ROWF + c, Wg + (size_t)r * K + c);
    }
}

template<int EPI>
__global__ __launch_bounds__(256, 1) void tc_gemm(
    const float* __restrict__ A, const float* __restrict__ W,
    const float* __restrict__ bias, const float* __restrict__ res,
    float* __restrict__ C, int N, int K)
{
    extern __shared__ float smemf[];
    int tid  = threadIdx.x;
    int wid  = tid >> 5;
    int lane = tid & 31;
    int wm   = wid & 3;          // 0..3  (M direction, 32 rows each)
    int wn   = wid >> 2;         // 0..1  (N direction, 64 cols each)
    int m0   = blockIdx.y * BM;
    int n0   = blockIdx.x * BN;

    float acc[2][8][4];
    #pragma unroll
    for (int fm = 0; fm < 2; fm++)
        #pragma unroll
        for (int fn = 0; fn < 8; fn++)
            #pragma unroll
            for (int e = 0; e < 4; e++) acc[fm][fn][e] = 0.f;

    const int NK = K / BK;

    gemm_load_stage<EPI>(smemf, 0, 0, A, W, m0, n0, K, tid);
    asm volatile("cp.async.commit_group;" ::: "memory");
    gemm_load_stage<EPI>(smemf, 1, 1, A, W, m0, n0, K, tid);
    asm volatile("cp.async.commit_group;" ::: "memory");

    int lr = lane >> 2;          // 0..7
    int lc = lane & 3;           // 0..3

    for (int kt = 0; kt < NK; kt++) {
        int s = kt % GSTAGES;
        asm volatile("cp.async.wait_group 1;" ::: "memory");
        __syncthreads();

        // Prefetch stage kt+2 (slot was last computed at kt-1; the barrier
        // above guarantees every warp has finished compute(kt-1)).
        int kn = kt + 2;
        if (kn < NK)
            gemm_load_stage<EPI>(smemf, kn % GSTAGES, kn, A, W, m0, n0, K, tid);
        asm volatile("cp.async.commit_group;" ::: "memory");

        const float* As = smemf + s * STAGEF;
        const float* Bs = smemf + (GSTAGES + s) * STAGEF;

        #pragma unroll
        for (int k = 0; k < BK; k += 8) {
            uint32_t a[2][4], b[8][2];
            #pragma unroll
            for (int fm = 0; fm < 2; fm++) {
                const float* ap = As + (wm * 32 + fm * 16 + lr) * ROWF + k + lc;
                a[fm][0] = __float_as_uint(ap[0]);
                a[fm][1] = __float_as_uint(ap[8 * ROWF]);
                a[fm][2] = __float_as_uint(ap[4]);
                a[fm][3] = __float_as_uint(ap[8 * ROWF + 4]);
            }
            #pragma unroll
            for (int fn = 0; fn < 8; fn++) {
                const float* bp = Bs + (wn * 64 + fn * 8 + lr) * ROWF + k + lc;
                b[fn][0] = __float_as_uint(bp[0]);
                b[fn][1] = __float_as_uint(bp[4]);
            }
            #pragma unroll
            for (int fm = 0; fm < 2; fm++)
                #pragma unroll
                for (int fn = 0; fn < 8; fn++)
                    mma_tf32(acc[fm][fn], a[fm], b[fn]);
        }
        __syncthreads();
    }

    // Epilogue. acc[fm][fn] = {c0,c1 (row r), c2,c3 (row r+8)}, cols 2*lc, 2*lc+1
    #pragma unroll
    for (int fm = 0; fm < 2; fm++) {
        #pragma unroll
        for (int fn = 0; fn < 8; fn++) {
            int rowa = m0 + wm * 32 + fm * 16 + lr;
            int colg = n0 + wn * 64 + fn * 8 + 2 * lc;
            float bx = bias[colg], by = bias[colg + 1];
            #pragma unroll
            for (int half = 0; half < 2; half++) {
                int rr = rowa + half * 8;
                float vx = acc[fm][fn][half * 2 + 0] + bx;
                float vy = acc[fm][fn][half * 2 + 1] + by;
                if (EPI == 1) { vx = tf32r(gelu_exact(vx)); vy = tf32r(gelu_exact(vy)); }
                if (EPI == 2) {
                    const float2 rv = *(const float2*)&res[(size_t)rr * N + colg];
                    vx += rv.x; vy += rv.y;
                }
                *(float2*)&C[(size_t)rr * N + colg] = make_float2(vx, vy);
            }
        }
    }
}

// ---------------------------------------------------------------------------
// LayerNorm: one block per row (D=1024), 256 threads, tf32-rounded output.
// ---------------------------------------------------------------------------
__global__ void ln_kernel(const float* __restrict__ x, const float* __restrict__ g,
                          const float* __restrict__ beta, float* __restrict__ out)
{
    int row = blockIdx.x;
    int tid = threadIdx.x;
    const float4* xr = (const float4*)(x + (size_t)row * Dv);
    float4 v = xr[tid];
    float s  = v.x + v.y + v.z + v.w;
    float sq = v.x*v.x + v.y*v.y + v.z*v.z + v.w*v.w;
    #pragma unroll
    for (int o = 16; o > 0; o >>= 1) {
        s  += __shfl_xor_sync(0xffffffffu, s, o);
        sq += __shfl_xor_sync(0xffffffffu, sq, o);
    }
    __shared__ float rs[8], rq[8];
    __shared__ float smean, srstd;
    int w = tid >> 5;
    if ((tid & 31) == 0) { rs[w] = s; rq[w] = sq; }
    __syncthreads();
    if (tid == 0) {
        float ts = 0.f, tq = 0.f;
        #pragma unroll
        for (int i = 0; i < 8; i++) { ts += rs[i]; tq += rq[i]; }
        float mean = ts * (1.0f / Dv);
        float var  = tq * (1.0f / Dv) - mean * mean;
        smean = mean;
        srstd = rsqrtf(var + 1e-5f);
    }
    __syncthreads();
    float mean = smean, rstd = srstd;
    float4 gg = ((const float4*)g)[tid];
    float4 bb = ((const float4*)beta)[tid];
    float4 o4;
    o4.x = tf32r((v.x - mean) * rstd * gg.x + bb.x);
    o4.y = tf32r((v.y - mean) * rstd * gg.y + bb.y);
    o4.z = tf32r((v.z - mean) * rstd * gg.z + bb.z);
    o4.w = tf32r((v.w - mean) * rstd * gg.w + bb.w);
    ((float4*)(out + (size_t)row * Dv))[tid] = o4;
}

// ---------------------------------------------------------------------------
// Flash-style banded attention (fp32 SIMT), tf32-rounded output.
// ---------------------------------------------------------------------------
__global__ void attn_kernel(const float* __restrict__ qkv, float* __restrict__ o)
{
    extern __shared__ float smemf[];
    float* Qs  = smemf;
    float* Kst = smemf + 4096;
    float* Vs  = smemf + 8192;
    float* Ps  = smemf + 12288;

    int tid  = threadIdx.x;
    int lane = tid & 31;
    int w    = tid >> 5;
    int q0   = blockIdx.x * 64;
    int h    = blockIdx.y;
    int b    = blockIdx.z;

    const float SCALE = 0.125f * 1.4426950408889634f;

    for (int i = tid; i < 64 * 16; i += 256) {
        int row = i >> 4;
        int c4  = (i & 15) << 2;
        float4 q = *(const float4*)&qkv[(size_t)(b * Tv + q0 + row) * 3072 + h * 64 + c4];
        float* dst = &Qs[row * 64 + c4];
        dst[0] = q.x * SCALE; dst[1] = q.y * SCALE;
        dst[2] = q.z * SCALE; dst[3] = q.w * SCALE;
    }

    float s[8][2], oacc[8][2], mrow[8], lrow[8];
    #pragma unroll
    for (int r = 0; r < 8; r++) {
        oacc[r][0] = 0.f; oacc[r][1] = 0.f;
        mrow[r] = -1e30f; lrow[r] = 0.f;
    }

    int kmax   = min(q0 + 64 + WINDOWv, Tv);
    int ntiles = (kmax + 63) >> 6;

    for (int kt = 0; kt < ntiles; kt++) {
        int k0 = kt << 6;
        __syncthreads();
        for (int i = tid; i < 64 * 16; i += 256) {
            int row = i >> 4;
            int c4  = (i & 15) << 2;
            const float* base = &qkv[(size_t)(b * Tv + k0 + row) * 3072 + h * 64 + c4];
            float4 kk = *(const float4*)(base + 1024);
            Kst[(c4+0)*64 + row] = kk.x;
            Kst[(c4+1)*64 + row] = kk.y;
            Kst[(c4+2)*64 + row] = kk.z;
            Kst[(c4+3)*64 + row] = kk.w;
            float4 vv = *(const float4*)(base + 2048);
            *(float4*)&Vs[row * 64 + c4] = vv;
        }
        __syncthreads();

        #pragma unroll
        for (int r = 0; r < 8; r++) { s[r][0] = 0.f; s[r][1] = 0.f; }

        #pragma unroll 8
        for (int d = 0; d < 64; d += 2) {
            float2 ka = *(float2*)&Kst[d * 64 + 2 * lane];
            float2 kb = *(float2*)&Kst[(d + 1) * 64 + 2 * lane];
            #pragma unroll
            for (int r = 0; r < 8; r++) {
                float2 q = *(float2*)&Qs[(w * 8 + r) * 64 + d];
                s[r][0] += q.x * ka.x + q.y * kb.x;
                s[r][1] += q.x * ka.y + q.y * kb.y;
            }
        }

        int j0 = k0 + 2 * lane;
        #pragma unroll
        for (int r = 0; r < 8; r++) {
            int iq = q0 + w * 8 + r;
            float s0 = (j0     <= iq + WINDOWv) ? s[r][0] : -1e30f;
            float s1 = (j0 + 1 <= iq + WINDOWv) ? s[r][1] : -1e30f;
            float mx = fmaxf(s0, s1);
            #pragma unroll
            for (int off = 16; off > 0; off >>= 1)
                mx = fmaxf(mx, __shfl_xor_sync(0xffffffffu, mx, off));
            float mnew = fmaxf(mrow[r], mx);
            float corr = exp2f(mrow[r] - mnew);
            float p0 = exp2f(s0 - mnew);
            float p1 = exp2f(s1 - mnew);
            float ps = p0 + p1;
            #pragma unroll
            for (int off = 16; off > 0; off >>= 1)
                ps += __shfl_xor_sync(0xffffffffu, ps, off);
            lrow[r] = lrow[r] * corr + ps;
            oacc[r][0] *= corr;
            oacc[r][1] *= corr;
            mrow[r] = mnew;
            *(float2*)&Ps[(w * 8 + r) * 64 + 2 * lane] = make_float2(p0, p1);
        }
        __syncwarp();

        #pragma unroll 8
        for (int j = 0; j < 64; j += 2) {
            float2 va = *(float2*)&Vs[j * 64 + 2 * lane];
            float2 vb = *(float2*)&Vs[(j + 1) * 64 + 2 * lane];
            #pragma unroll
            for (int r = 0; r < 8; r++) {
                float2 p = *(float2*)&Ps[(w * 8 + r) * 64 + j];
                oacc[r][0] += p.x * va.x + p.y * vb.x;
                oacc[r][1] += p.x * va.y + p.y * vb.y;
            }
        }
        __syncwarp();
    }

    #pragma unroll
    for (int r = 0; r < 8; r++) {
        float inv = 1.0f / lrow[r];
        float2 ov = make_float2(tf32r(oacc[r][0] * inv), tf32r(oacc[r][1] * inv));
        *(float2*)&o[(size_t)(b * Tv + q0 + w * 8 + r) * Dv + h * 64 + 2 * lane] = ov;
    }
}

// ---------------------------------------------------------------------------
// Launch
// ---------------------------------------------------------------------------
extern "C" void kernel_launch(void* const* d_in, const int* in_sizes, int n_in,
                              void* d_out, int out_size)
{
    const float* x     = (const float*)d_in[0];
    const float* in_w  = (const float*)d_in[1];
    const float* in_b  = (const float*)d_in[2];
    const float* out_w = (const float*)d_in[3];
    const float* out_b = (const float*)d_in[4];
    const float* ln1g  = (const float*)d_in[5];
    const float* ln1b  = (const float*)d_in[6];
    const float* w1    = (const float*)d_in[7];
    const float* b1    = (const float*)d_in[8];
    const float* w2    = (const float*)d_in[9];
    const float* b2    = (const float*)d_in[10];
    const float* ln2g  = (const float*)d_in[11];
    const float* ln2b  = (const float*)d_in[12];
    float* out = (float*)d_out;

    float *h, *qkv, *o, *ff, *wqkv, *wout, *w1r, *w2r;
    cudaGetSymbolAddress((void**)&h,    g_h);
    cudaGetSymbolAddress((void**)&qkv,  g_qkv);
    cudaGetSymbolAddress((void**)&o,    g_o);
    cudaGetSymbolAddress((void**)&ff,   g_ff);
    cudaGetSymbolAddress((void**)&wqkv, g_wqkv);
    cudaGetSymbolAddress((void**)&wout, g_wout);
    cudaGetSymbolAddress((void**)&w1r,  g_w1r);
    cudaGetSymbolAddress((void**)&w2r,  g_w2r);

    const int SMEM_GEMM = SMEM_FLOATS * 4;   // 110592 B
    cudaFuncSetAttribute(attn_kernel, cudaFuncAttributeMaxDynamicSharedMemorySize, 64 * 1024);
    cudaFuncSetAttribute(tc_gemm<0>, cudaFuncAttributeMaxDynamicSharedMemorySize, SMEM_GEMM);
    cudaFuncSetAttribute(tc_gemm<1>, cudaFuncAttributeMaxDynamicSharedMemorySize, SMEM_GEMM);
    cudaFuncSetAttribute(tc_gemm<2>, cudaFuncAttributeMaxDynamicSharedMemorySize, SMEM_GEMM);

    // 0) tf32-round all weights into scratch
    round_w_kernel<<<264, 256>>>((const float4*)in_w,  (float4*)wqkv, 3 * Dv * Dv / 4);
    round_w_kernel<<<264, 256>>>((const float4*)out_w, (float4*)wout, Dv * Dv / 4);
    round_w_kernel<<<264, 256>>>((const float4*)w1,    (float4*)w1r,  4 * Dv * Dv / 4);
    round_w_kernel<<<264, 256>>>((const float4*)w2,    (float4*)w2r,  Dv * 4 * Dv / 4);

    // 1) h = LN1(x)  (tf32-rounded)
    ln_kernel<<<Mv, 256>>>(x, ln1g, ln1b, h);

    // 2) qkv = h @ in_proj_w^T + in_proj_b     [4096, 3072]
    tc_gemm<0><<<dim3(3072 / BN, Mv / BM), 256, SMEM_GEMM>>>(h, wqkv, in_b, nullptr, qkv, 3072, 1024);

    // 3) o = banded_flash_attention(qkv)       [4096, 1024] (tf32-rounded)
    attn_kernel<<<dim3(Tv / 64, Hv, Bv), 256, 64 * 1024>>>(qkv, o);

    // 4) x1 = o @ out_w^T + out_b + x  -> d_out
    tc_gemm<2><<<dim3(1024 / BN, Mv / BM), 256, SMEM_GEMM>>>(o, wout, out_b, x, out, 1024, 1024);

    // 5) h2 = LN2(x1)  (tf32-rounded)
    ln_kernel<<<Mv, 256>>>(out, ln2g, ln2b, h);

    // 6) ff = GELU(h2 @ w1^T + b1)             [4096, 4096] (tf32-rounded)
    tc_gemm<1><<<dim3(4096 / BN, Mv / BM), 256, SMEM_GEMM>>>(h, w1r, b1, nullptr, ff, 4096, 1024);

    // 7) out = ff @ w2^T + b2 + x1  (in-place residual on d_out)
    tc_gemm<2><<<dim3(1024 / BN, Mv / BM), 256, SMEM_GEMM>>>(ff, w2r, b2, out, out, 1024, 4096);
}

// round 4
// speedup vs baseline: 2.8568x; 1.4231x over previous
#include <cuda_runtime.h>
#include <math.h>
#include <cstdint>

// Problem constants
#define Bv 2
#define Tv 2048
#define Dv 1024
#define Hv 16
#define Mv 4096          // B*T
#define WINDOWv 10

// ---------------------------------------------------------------------------
// Scratch (static __device__ arrays; no allocation allowed)
// ---------------------------------------------------------------------------
__device__ float g_h  [Mv * Dv];          // LN output (tf32-rounded)
__device__ float g_qkv[Mv * 3 * Dv];      // QKV projection output
__device__ float g_o  [Mv * Dv];          // attention output (tf32-rounded)
__device__ float g_ff [Mv * 4 * Dv];      // FFN hidden (tf32-rounded)
__device__ float g_vt [Bv * Hv * 64 * Tv];// V transposed: [b][h][d][t], tf32-rounded
__device__ float g_wqkv[3 * Dv * Dv];     // tf32-rounded weights
__device__ float g_wout[Dv * Dv];
__device__ float g_w1r [4 * Dv * Dv];
__device__ float g_w2r [Dv * 4 * Dv];

// ---------------------------------------------------------------------------
// Helpers
// ---------------------------------------------------------------------------
__device__ __forceinline__ float tf32r(float x) {
    uint32_t r;
    asm("cvt.rna.tf32.f32 %0, %1;" : "=r"(r) : "f"(x));
    return __uint_as_float(r);
}

__device__ __forceinline__ void cp16(void* dst, const void* src) {
    uint32_t d;
    asm("{ .reg .u64 t; cvta.to.shared.u64 t, %1; cvt.u32.u64 %0, t; }" : "=r"(d) : "l"(dst));
    asm volatile("cp.async.cg.shared.global [%0], [%1], 16;" :: "r"(d), "l"(src) : "memory");
}

__device__ __forceinline__ float gelu_exact(float x) {
    return 0.5f * x * (1.0f + erff(x * 0.70710678118654752f));
}

// m16n8k8 tf32 mma, fp32 accumulate
__device__ __forceinline__ void mma_tf32(float* c, const uint32_t* a, const uint32_t* b) {
    asm volatile(
        "mma.sync.aligned.m16n8k8.row.col.f32.tf32.tf32.f32 "
        "{%0,%1,%2,%3}, {%4,%5,%6,%7}, {%8,%9}, {%0,%1,%2,%3};"
        : "+f"(c[0]), "+f"(c[1]), "+f"(c[2]), "+f"(c[3])
        : "r"(a[0]), "r"(a[1]), "r"(a[2]), "r"(a[3]), "r"(b[0]), "r"(b[1]));
}

// ---------------------------------------------------------------------------
// Weight tf32-rounding prep
// ---------------------------------------------------------------------------
__global__ void round_w_kernel(const float4* __restrict__ in, float4* __restrict__ out, int n4) {
    int i = blockIdx.x * blockDim.x + threadIdx.x;
    int stride = gridDim.x * blockDim.x;
    for (; i < n4; i += stride) {
        float4 v = in[i];
        v.x = tf32r(v.x); v.y = tf32r(v.y); v.z = tf32r(v.z); v.w = tf32r(v.w);
        out[i] = v;
    }
}

// ---------------------------------------------------------------------------
// V transpose: g_vt[b][h][d][t] = tf32r(qkv[b][t][2048 + h*64 + d])
// 32x32 tiles, block (32,8).
// ---------------------------------------------------------------------------
__global__ void vt_kernel(const float* __restrict__ qkv, float* __restrict__ vt)
{
    __shared__ float tile[32][33];
    int t0  = blockIdx.x * 32;
    int dg0 = blockIdx.y * 32;          // global V dim (0..1023)
    int b   = blockIdx.z;
    int tx  = threadIdx.x, ty = threadIdx.y;
    #pragma unroll
    for (int i = 0; i < 4; i++) {
        int t = t0 + ty + i * 8;
        tile[ty + i * 8][tx] = qkv[(size_t)(b * Tv + t) * 3072 + 2048 + dg0 + tx];
    }
    __syncthreads();
    #pragma unroll
    for (int i = 0; i < 4; i++) {
        int dg = dg0 + ty + i * 8;
        int h = dg >> 6, d = dg & 63;
        vt[(size_t)((b * Hv + h) * 64 + d) * Tv + t0 + tx] = tf32r(tile[tx][ty + i * 8]);
    }
}

// ---------------------------------------------------------------------------
// tf32 mma.sync GEMM: C[M,N] = A[M,K] * W[N,K]^T + bias (+ epilogue)
//   EPI 0: bias   EPI 1: bias + GELU (tf32-rounded)   EPI 2: bias + residual
// CTA tile 128x128, BK=32, 8 warps (4 along M x 2 along N), warp tile 32x64.
// ---------------------------------------------------------------------------
#define BM 128
#define BN 128
#define BK 32
#define GSTAGES 3
#define ROWF 36
#define STAGEF (128 * ROWF)
#define SMEM_FLOATS (2 * GSTAGES * STAGEF)

template<int EPI>
__device__ __forceinline__ void gemm_load_stage(float* smemf, int slot, int kt,
                                                const float* __restrict__ A,
                                                const float* __restrict__ W,
                                                int m0, int n0, int K, int tid)
{
    float* As = smemf + slot * STAGEF;
    float* Bs = smemf + (GSTAGES + slot) * STAGEF;
    int k0 = kt * BK;
    const float* Ag = A + (size_t)m0 * K + k0;
    const float* Wg = W + (size_t)n0 * K + k0;
    #pragma unroll
    for (int i = 0; i < 4; i++) {
        int idx = tid + i * 256;
        int r = idx >> 3, c = (idx & 7) << 2;
        cp16(As + r * ROWF + c, Ag + (size_t)r * K + c);
    }
    #pragma unroll
    for (int i = 0; i < 4; i++) {
        int idx = tid + i * 256;
        int r = idx >> 3, c = (idx & 7) << 2;
        cp16(Bs + r * ROWF + c, Wg + (size_t)r * K + c);
    }
}

template<int EPI>
__global__ __launch_bounds__(256, 1) void tc_gemm(
    const float* __restrict__ A, const float* __restrict__ W,
    const float* __restrict__ bias, const float* __restrict__ res,
    float* __restrict__ C, int N, int K)
{
    extern __shared__ float smemf[];
    int tid  = threadIdx.x;
    int wid  = tid >> 5;
    int lane = tid & 31;
    int wm   = wid & 3;
    int wn   = wid >> 2;
    int m0   = blockIdx.y * BM;
    int n0   = blockIdx.x * BN;

    float acc[2][8][4];
    #pragma unroll
    for (int fm = 0; fm < 2; fm++)
        #pragma unroll
        for (int fn = 0; fn < 8; fn++)
            #pragma unroll
            for (int e = 0; e < 4; e++) acc[fm][fn][e] = 0.f;

    const int NK = K / BK;

    gemm_load_stage<EPI>(smemf, 0, 0, A, W, m0, n0, K, tid);
    asm volatile("cp.async.commit_group;" ::: "memory");
    gemm_load_stage<EPI>(smemf, 1, 1, A, W, m0, n0, K, tid);
    asm volatile("cp.async.commit_group;" ::: "memory");

    int lr = lane >> 2;
    int lc = lane & 3;

    for (int kt = 0; kt < NK; kt++) {
        int s = kt % GSTAGES;
        asm volatile("cp.async.wait_group 1;" ::: "memory");
        __syncthreads();

        int kn = kt + 2;
        if (kn < NK)
            gemm_load_stage<EPI>(smemf, kn % GSTAGES, kn, A, W, m0, n0, K, tid);
        asm volatile("cp.async.commit_group;" ::: "memory");

        const float* As = smemf + s * STAGEF;
        const float* Bs = smemf + (GSTAGES + s) * STAGEF;

        #pragma unroll
        for (int k = 0; k < BK; k += 8) {
            uint32_t a[2][4], b[8][2];
            #pragma unroll
            for (int fm = 0; fm < 2; fm++) {
                const float* ap = As + (wm * 32 + fm * 16 + lr) * ROWF + k + lc;
                a[fm][0] = __float_as_uint(ap[0]);
                a[fm][1] = __float_as_uint(ap[8 * ROWF]);
                a[fm][2] = __float_as_uint(ap[4]);
                a[fm][3] = __float_as_uint(ap[8 * ROWF + 4]);
            }
            #pragma unroll
            for (int fn = 0; fn < 8; fn++) {
                const float* bp = Bs + (wn * 64 + fn * 8 + lr) * ROWF + k + lc;
                b[fn][0] = __float_as_uint(bp[0]);
                b[fn][1] = __float_as_uint(bp[4]);
            }
            #pragma unroll
            for (int fm = 0; fm < 2; fm++)
                #pragma unroll
                for (int fn = 0; fn < 8; fn++)
                    mma_tf32(acc[fm][fn], a[fm], b[fn]);
        }
        __syncthreads();
    }

    #pragma unroll
    for (int fm = 0; fm < 2; fm++) {
        #pragma unroll
        for (int fn = 0; fn < 8; fn++) {
            int rowa = m0 + wm * 32 + fm * 16 + lr;
            int colg = n0 + wn * 64 + fn * 8 + 2 * lc;
            float bx = bias[colg], by = bias[colg + 1];
            #pragma unroll
            for (int half = 0; half < 2; half++) {
                int rr = rowa + half * 8;
                float vx = acc[fm][fn][half * 2 + 0] + bx;
                float vy = acc[fm][fn][half * 2 + 1] + by;
                if (EPI == 1) { vx = tf32r(gelu_exact(vx)); vy = tf32r(gelu_exact(vy)); }
                if (EPI == 2) {
                    const float2 rv = *(const float2*)&res[(size_t)rr * N + colg];
                    vx += rv.x; vy += rv.y;
                }
                *(float2*)&C[(size_t)rr * N + colg] = make_float2(vx, vy);
            }
        }
    }
}

// ---------------------------------------------------------------------------
// LayerNorm: one block per row (D=1024), 256 threads, tf32-rounded output.
// ---------------------------------------------------------------------------
__global__ void ln_kernel(const float* __restrict__ x, const float* __restrict__ g,
                          const float* __restrict__ beta, float* __restrict__ out)
{
    int row = blockIdx.x;
    int tid = threadIdx.x;
    const float4* xr = (const float4*)(x + (size_t)row * Dv);
    float4 v = xr[tid];
    float s  = v.x + v.y + v.z + v.w;
    float sq = v.x*v.x + v.y*v.y + v.z*v.z + v.w*v.w;
    #pragma unroll
    for (int o = 16; o > 0; o >>= 1) {
        s  += __shfl_xor_sync(0xffffffffu, s, o);
        sq += __shfl_xor_sync(0xffffffffu, sq, o);
    }
    __shared__ float rs[8], rq[8];
    __shared__ float smean, srstd;
    int w = tid >> 5;
    if ((tid & 31) == 0) { rs[w] = s; rq[w] = sq; }
    __syncthreads();
    if (tid == 0) {
        float ts = 0.f, tq = 0.f;
        #pragma unroll
        for (int i = 0; i < 8; i++) { ts += rs[i]; tq += rq[i]; }
        float mean = ts * (1.0f / Dv);
        float var  = tq * (1.0f / Dv) - mean * mean;
        smean = mean;
        srstd = rsqrtf(var + 1e-5f);
    }
    __syncthreads();
    float mean = smean, rstd = srstd;
    float4 gg = ((const float4*)g)[tid];
    float4 bb = ((const float4*)beta)[tid];
    float4 o4;
    o4.x = tf32r((v.x - mean) * rstd * gg.x + bb.x);
    o4.y = tf32r((v.y - mean) * rstd * gg.y + bb.y);
    o4.z = tf32r((v.z - mean) * rstd * gg.z + bb.z);
    o4.w = tf32r((v.w - mean) * rstd * gg.w + bb.w);
    ((float4*)(out + (size_t)row * Dv))[tid] = o4;
}

// ---------------------------------------------------------------------------
// Tensor-core flash attention, banded (causal + 10 lookahead).
// CTA = 128 queries x 1 head. 8 warps, each owns 16 query rows.
// Key tiles of 64. QK^T and PV via mma.sync tf32; softmax on fragments,
// P through smem (own warp only). Heavy q-tiles scheduled first.
// Smem (floats, pad 68): Qs[128][68] Ks[64][68] Vt[64][68] Ps[128][68].
// ---------------------------------------------------------------------------
#define APAD 68
#define AQ_OFF 0
#define AK_OFF (128 * APAD)                 // 8704
#define AV_OFF (AK_OFF + 64 * APAD)        // 13056
#define AP_OFF (AV_OFF + 64 * APAD)        // 17408
#define ASMEM_FLOATS (AP_OFF + 128 * APAD) // 26112 floats = 104448 B

__global__ __launch_bounds__(256, 1) void attn_tc_kernel(
    const float* __restrict__ qkv, const float* __restrict__ vt, float* __restrict__ o)
{
    extern __shared__ float sm[];
    float* Qs = sm + AQ_OFF;
    float* Ks = sm + AK_OFF;
    float* Vs = sm + AV_OFF;
    float* Ps = sm + AP_OFF;

    int tid  = threadIdx.x;
    int lane = tid & 31;
    int wq   = tid >> 5;           // warp: query group 0..7
    int lr   = lane >> 2;          // 0..7
    int lc   = lane & 3;           // 0..3
    int qt   = 15 - blockIdx.x;    // heavy tiles first
    int q0   = qt * 128;
    int h    = blockIdx.y;
    int b    = blockIdx.z;

    const float SCALE = 0.125f * 1.4426950408889634f;  // 1/sqrt(64) * log2(e)

    // Load Q tile (pre-scaled, tf32-rounded)
    for (int i = tid; i < 128 * 16; i += 256) {
        int row = i >> 4;
        int c4  = (i & 15) << 2;
        float4 q = *(const float4*)&qkv[(size_t)(b * Tv + q0 + row) * 3072 + h * 64 + c4];
        float4 r;
        r.x = tf32r(q.x * SCALE); r.y = tf32r(q.y * SCALE);
        r.z = tf32r(q.z * SCALE); r.w = tf32r(q.w * SCALE);
        *(float4*)&Qs[row * APAD + c4] = r;
    }

    int r0  = wq * 16 + lr;         // local row (first of pair)
    int iq0 = q0 + r0;
    int iq1 = iq0 + 8;
    int lim0 = iq0 + WINDOWv;
    int lim1 = iq1 + WINDOWv;

    float m0 = -1e30f, m1 = -1e30f, l0 = 0.f, l1 = 0.f;
    float oacc[8][4];
    #pragma unroll
    for (int nf = 0; nf < 8; nf++)
        #pragma unroll
        for (int e = 0; e < 4; e++) oacc[nf][e] = 0.f;

    int kmax   = min(q0 + 128 + WINDOWv, Tv);
    int ntiles = (kmax + 63) >> 6;

    const float* vbase = vt + (size_t)((b * Hv + h) * 64) * Tv;

    for (int kt = 0; kt < ntiles; kt++) {
        int k0 = kt << 6;
        __syncthreads();
        // Load K tile [j][d] (tf32-rounded) and V^T tile [d][j] (pre-rounded)
        for (int i = tid; i < 64 * 16; i += 256) {
            int row = i >> 4;
            int c4  = (i & 15) << 2;
            float4 kk = *(const float4*)&qkv[(size_t)(b * Tv + k0 + row) * 3072 + 1024 + h * 64 + c4];
            float4 r;
            r.x = tf32r(kk.x); r.y = tf32r(kk.y); r.z = tf32r(kk.z); r.w = tf32r(kk.w);
            *(float4*)&Ks[row * APAD + c4] = r;
            float4 vv = *(const float4*)&vbase[(size_t)row * Tv + k0 + c4];  // row=d, c4=j
            *(float4*)&Vs[row * APAD + c4] = vv;
        }
        __syncthreads();

        // S = Q K^T
        float sacc[8][4];
        #pragma unroll
        for (int jf = 0; jf < 8; jf++)
            #pragma unroll
            for (int e = 0; e < 4; e++) sacc[jf][e] = 0.f;

        #pragma unroll
        for (int kd = 0; kd < 64; kd += 8) {
            uint32_t a[4], bfr[8][2];
            const float* ap = Qs + r0 * APAD + kd + lc;
            a[0] = __float_as_uint(ap[0]);
            a[1] = __float_as_uint(ap[8 * APAD]);
            a[2] = __float_as_uint(ap[4]);
            a[3] = __float_as_uint(ap[8 * APAD + 4]);
            #pragma unroll
            for (int jf = 0; jf < 8; jf++) {
                const float* bp = Ks + (jf * 8 + lr) * APAD + kd + lc;
                bfr[jf][0] = __float_as_uint(bp[0]);
                bfr[jf][1] = __float_as_uint(bp[4]);
            }
            #pragma unroll
            for (int jf = 0; jf < 8; jf++)
                mma_tf32(sacc[jf], a, bfr[jf]);
        }

        // Mask + row max (rows r0, r0+8)
        int jbase = k0 + 2 * lc;
        float mx0 = -1e30f, mx1 = -1e30f;
        #pragma unroll
        for (int jf = 0; jf < 8; jf++) {
            int jA = jbase + jf * 8, jB = jA + 1;
            sacc[jf][0] = (jA <= lim0) ? sacc[jf][0] : -1e30f;
            sacc[jf][1] = (jB <= lim0) ? sacc[jf][1] : -1e30f;
            sacc[jf][2] = (jA <= lim1) ? sacc[jf][2] : -1e30f;
            sacc[jf][3] = (jB <= lim1) ? sacc[jf][3] : -1e30f;
            mx0 = fmaxf(mx0, fmaxf(sacc[jf][0], sacc[jf][1]));
            mx1 = fmaxf(mx1, fmaxf(sacc[jf][2], sacc[jf][3]));
        }
        mx0 = fmaxf(mx0, __shfl_xor_sync(0xffffffffu, mx0, 1));
        mx0 = fmaxf(mx0, __shfl_xor_sync(0xffffffffu, mx0, 2));
        mx1 = fmaxf(mx1, __shfl_xor_sync(0xffffffffu, mx1, 1));
        mx1 = fmaxf(mx1, __shfl_xor_sync(0xffffffffu, mx1, 2));

        float mn0 = fmaxf(m0, mx0), mn1 = fmaxf(m1, mx1);
        float corr0 = exp2f(m0 - mn0), corr1 = exp2f(m1 - mn1);

        float ps0 = 0.f, ps1 = 0.f;
        #pragma unroll
        for (int jf = 0; jf < 8; jf++) {
            float p00 = tf32r(exp2f(sacc[jf][0] - mn0));
            float p01 = tf32r(exp2f(sacc[jf][1] - mn0));
            float p10 = tf32r(exp2f(sacc[jf][2] - mn1));
            float p11 = tf32r(exp2f(sacc[jf][3] - mn1));
            ps0 += p00 + p01;
            ps1 += p10 + p11;
            *(float2*)&Ps[r0 * APAD + jf * 8 + 2 * lc]       = make_float2(p00, p01);
            *(float2*)&Ps[(r0 + 8) * APAD + jf * 8 + 2 * lc] = make_float2(p10, p11);
        }
        ps0 += __shfl_xor_sync(0xffffffffu, ps0, 1);
        ps0 += __shfl_xor_sync(0xffffffffu, ps0, 2);
        ps1 += __shfl_xor_sync(0xffffffffu, ps1, 1);
        ps1 += __shfl_xor_sync(0xffffffffu, ps1, 2);

        l0 = l0 * corr0 + ps0;
        l1 = l1 * corr1 + ps1;
        m0 = mn0; m1 = mn1;
        #pragma unroll
        for (int nf = 0; nf < 8; nf++) {
            oacc[nf][0] *= corr0; oacc[nf][1] *= corr0;
            oacc[nf][2] *= corr1; oacc[nf][3] *= corr1;
        }
        __syncwarp();

        // O += P V   (A = P from smem, B = V^T tile)
        #pragma unroll
        for (int kj = 0; kj < 64; kj += 8) {
            uint32_t a[4], bfr[8][2];
            const float* ap = Ps + r0 * APAD + kj + lc;
            a[0] = __float_as_uint(ap[0]);
            a[1] = __float_as_uint(ap[8 * APAD]);
            a[2] = __float_as_uint(ap[4]);
            a[3] = __float_as_uint(ap[8 * APAD + 4]);
            #pragma unroll
            for (int nf = 0; nf < 8; nf++) {
                const float* bp = Vs + (nf * 8 + lr) * APAD + kj + lc;
                bfr[nf][0] = __float_as_uint(bp[0]);
                bfr[nf][1] = __float_as_uint(bp[4]);
            }
            #pragma unroll
            for (int nf = 0; nf < 8; nf++)
                mma_tf32(oacc[nf], a, bfr[nf]);
        }
        __syncwarp();
    }

    // Normalize and store (tf32-rounded; feeds out-proj GEMM)
    float inv0 = 1.0f / l0, inv1 = 1.0f / l1;
    #pragma unroll
    for (int nf = 0; nf < 8; nf++) {
        int col = h * 64 + nf * 8 + 2 * lc;
        float2 v0 = make_float2(tf32r(oacc[nf][0] * inv0), tf32r(oacc[nf][1] * inv0));
        float2 v1 = make_float2(tf32r(oacc[nf][2] * inv1), tf32r(oacc[nf][3] * inv1));
        *(float2*)&o[(size_t)(b * Tv + iq0) * Dv + col] = v0;
        *(float2*)&o[(size_t)(b * Tv + iq1) * Dv + col] = v1;
    }
}

// ---------------------------------------------------------------------------
// Launch
// ---------------------------------------------------------------------------
extern "C" void kernel_launch(void* const* d_in, const int* in_sizes, int n_in,
                              void* d_out, int out_size)
{
    const float* x     = (const float*)d_in[0];
    const float* in_w  = (const float*)d_in[1];
    const float* in_b  = (const float*)d_in[2];
    const float* out_w = (const float*)d_in[3];
    const float* out_b = (const float*)d_in[4];
    const float* ln1g  = (const float*)d_in[5];
    const float* ln1b  = (const float*)d_in[6];
    const float* w1    = (const float*)d_in[7];
    const float* b1    = (const float*)d_in[8];
    const float* w2    = (const float*)d_in[9];
    const float* b2    = (const float*)d_in[10];
    const float* ln2g  = (const float*)d_in[11];
    const float* ln2b  = (const float*)d_in[12];
    float* out = (float*)d_out;

    float *h, *qkv, *o, *ff, *vt, *wqkv, *wout, *w1r, *w2r;
    cudaGetSymbolAddress((void**)&h,    g_h);
    cudaGetSymbolAddress((void**)&qkv,  g_qkv);
    cudaGetSymbolAddress((void**)&o,    g_o);
    cudaGetSymbolAddress((void**)&ff,   g_ff);
    cudaGetSymbolAddress((void**)&vt,   g_vt);
    cudaGetSymbolAddress((void**)&wqkv, g_wqkv);
    cudaGetSymbolAddress((void**)&wout, g_wout);
    cudaGetSymbolAddress((void**)&w1r,  g_w1r);
    cudaGetSymbolAddress((void**)&w2r,  g_w2r);

    const int SMEM_GEMM = SMEM_FLOATS * 4;         // 110592 B
    const int SMEM_ATTN = ASMEM_FLOATS * 4;        // 104448 B
    cudaFuncSetAttribute(attn_tc_kernel, cudaFuncAttributeMaxDynamicSharedMemorySize, SMEM_ATTN);
    cudaFuncSetAttribute(tc_gemm<0>, cudaFuncAttributeMaxDynamicSharedMemorySize, SMEM_GEMM);
    cudaFuncSetAttribute(tc_gemm<1>, cudaFuncAttributeMaxDynamicSharedMemorySize, SMEM_GEMM);
    cudaFuncSetAttribute(tc_gemm<2>, cudaFuncAttributeMaxDynamicSharedMemorySize, SMEM_GEMM);

    // 0) tf32-round all weights into scratch
    round_w_kernel<<<264, 256>>>((const float4*)in_w,  (float4*)wqkv, 3 * Dv * Dv / 4);
    round_w_kernel<<<264, 256>>>((const float4*)out_w, (float4*)wout, Dv * Dv / 4);
    round_w_kernel<<<264, 256>>>((const float4*)w1,    (float4*)w1r,  4 * Dv * Dv / 4);
    round_w_kernel<<<264, 256>>>((const float4*)w2,    (float4*)w2r,  Dv * 4 * Dv / 4);

    // 1) h = LN1(x)  (tf32-rounded)
    ln_kernel<<<Mv, 256>>>(x, ln1g, ln1b, h);

    // 2) qkv = h @ in_proj_w^T + in_proj_b     [4096, 3072]
    tc_gemm<0><<<dim3(3072 / BN, Mv / BM), 256, SMEM_GEMM>>>(h, wqkv, in_b, nullptr, qkv, 3072, 1024);

    // 3a) V transpose: g_vt[b][h][d][t]
    vt_kernel<<<dim3(Tv / 32, Dv / 32, Bv), dim3(32, 8)>>>(qkv, vt);

    // 3b) o = tensor-core banded flash attention
    attn_tc_kernel<<<dim3(Tv / 128, Hv, Bv), 256, SMEM_ATTN>>>(qkv, vt, o);

    // 4) x1 = o @ out_w^T + out_b + x  -> d_out
    tc_gemm<2><<<dim3(1024 / BN, Mv / BM), 256, SMEM_GEMM>>>(o, wout, out_b, x, out, 1024, 1024);

    // 5) h2 = LN2(x1)  (tf32-rounded)
    ln_kernel<<<Mv, 256>>>(out, ln2g, ln2b, h);

    // 6) ff = GELU(h2 @ w1^T + b1)             [4096, 4096]
    tc_gemm<1><<<dim3(4096 / BN, Mv / BM), 256, SMEM_GEMM>>>(h, w1r, b1, nullptr, ff, 4096, 1024);

    // 7) out = ff @ w2^T + b2 + x1  (in-place residual on d_out)
    tc_gemm<2><<<dim3(1024 / BN, Mv / BM), 256, SMEM_GEMM>>>(ff, w2r, b2, out, out, 1024, 4096);
}

// round 5
// speedup vs baseline: 3.1368x; 1.0980x over previous
#include <cuda_runtime.h>
#include <math.h>
#include <cstdint>

// Problem constants
#define Bv 2
#define Tv 2048
#define Dv 1024
#define Hv 16
#define Mv 4096          // B*T
#define WINDOWv 10

// ---------------------------------------------------------------------------
// Scratch (static __device__ arrays; no allocation allowed)
// ---------------------------------------------------------------------------
__device__ float g_h  [Mv * Dv];          // LN output (tf32-rounded)
__device__ float g_qkv[Mv * 3 * Dv];      // QKV projection output
__device__ float g_o  [Mv * Dv];          // attention output (tf32-rounded)
__device__ float g_ff [Mv * 4 * Dv];      // FFN hidden (tf32-rounded)
__device__ float g_vt [Bv * Hv * 64 * Tv];// V transposed: [b][h][d][t], tf32-rounded
__device__ float g_wqkv[3 * Dv * Dv];     // tf32-rounded weights
__device__ float g_wout[Dv * Dv];
__device__ float g_w1r [4 * Dv * Dv];
__device__ float g_w2r [Dv * 4 * Dv];

// ---------------------------------------------------------------------------
// Helpers
// ---------------------------------------------------------------------------
__device__ __forceinline__ float tf32r(float x) {
    uint32_t r;
    asm("cvt.rna.tf32.f32 %0, %1;" : "=r"(r) : "f"(x));
    return __uint_as_float(r);
}

__device__ __forceinline__ void cp16(void* dst, const void* src) {
    uint32_t d;
    asm("{ .reg .u64 t; cvta.to.shared.u64 t, %1; cvt.u32.u64 %0, t; }" : "=r"(d) : "l"(dst));
    asm volatile("cp.async.cg.shared.global [%0], [%1], 16;" :: "r"(d), "l"(src) : "memory");
}

__device__ __forceinline__ float gelu_exact(float x) {
    return 0.5f * x * (1.0f + erff(x * 0.70710678118654752f));
}

// m16n8k8 tf32 mma, fp32 accumulate
__device__ __forceinline__ void mma_tf32(float* c, const uint32_t* a, const uint32_t* b) {
    asm volatile(
        "mma.sync.aligned.m16n8k8.row.col.f32.tf32.tf32.f32 "
        "{%0,%1,%2,%3}, {%4,%5,%6,%7}, {%8,%9}, {%0,%1,%2,%3};"
        : "+f"(c[0]), "+f"(c[1]), "+f"(c[2]), "+f"(c[3])
        : "r"(a[0]), "r"(a[1]), "r"(a[2]), "r"(a[3]), "r"(b[0]), "r"(b[1]));
}

// ---------------------------------------------------------------------------
// Fused weight tf32-rounding prep: all 4 weight matrices in one launch.
// Segment sizes in float4 units: 3M/4, 1M/4, 4M/4, 4M/4 (total 3M float4).
// ---------------------------------------------------------------------------
__global__ void round_all_kernel(const float4* __restrict__ i0, float4* __restrict__ o0,
                                 const float4* __restrict__ i1, float4* __restrict__ o1,
                                 const float4* __restrict__ i2, float4* __restrict__ o2,
                                 const float4* __restrict__ i3, float4* __restrict__ o3)
{
    const int n0 = 3 * Dv * Dv / 4;
    const int n1 = Dv * Dv / 4;
    const int n2 = 4 * Dv * Dv / 4;
    const int n3 = 4 * Dv * Dv / 4;
    const int total = n0 + n1 + n2 + n3;
    int stride = gridDim.x * blockDim.x;
    for (int i = blockIdx.x * blockDim.x + threadIdx.x; i < total; i += stride) {
        const float4* in; float4* out; int idx = i;
        if (idx < n0)                { in = i0; out = o0; }
        else if ((idx -= n0) < n1)   { in = i1; out = o1; }
        else if ((idx -= n1) < n2)   { in = i2; out = o2; }
        else { idx -= n2;              in = i3; out = o3; }
        float4 v = in[idx];
        v.x = tf32r(v.x); v.y = tf32r(v.y); v.z = tf32r(v.z); v.w = tf32r(v.w);
        out[idx] = v;
    }
}

// ---------------------------------------------------------------------------
// V transpose: g_vt[b][h][d][t] = tf32r(qkv[b][t][2048 + h*64 + d])
// ---------------------------------------------------------------------------
__global__ void vt_kernel(const float* __restrict__ qkv, float* __restrict__ vt)
{
    __shared__ float tile[32][33];
    int t0  = blockIdx.x * 32;
    int dg0 = blockIdx.y * 32;
    int b   = blockIdx.z;
    int tx  = threadIdx.x, ty = threadIdx.y;
    #pragma unroll
    for (int i = 0; i < 4; i++) {
        int t = t0 + ty + i * 8;
        tile[ty + i * 8][tx] = qkv[(size_t)(b * Tv + t) * 3072 + 2048 + dg0 + tx];
    }
    __syncthreads();
    #pragma unroll
    for (int i = 0; i < 4; i++) {
        int dg = dg0 + ty + i * 8;
        int h = dg >> 6, d = dg & 63;
        vt[(size_t)((b * Hv + h) * 64 + d) * Tv + t0 + tx] = tf32r(tile[tx][ty + i * 8]);
    }
}

// ---------------------------------------------------------------------------
// tf32 mma.sync GEMM: C[M,N] = A[M,K] * W[N,K]^T + bias (+ epilogue)
//   EPI 0: bias   EPI 1: bias + GELU (tf32-rounded)   EPI 2: bias + residual
// CTA tile 128x128, BK=32, 8 warps (4 M x 2 N), warp tile 32x64.
// 3-stage cp.async pipeline; 2 CTAs/SM (221 KB smem, <=128 regs).
// ---------------------------------------------------------------------------
#define BM 128
#define BN 128
#define BK 32
#define GSTAGES 3
#define ROWF 36
#define STAGEF (128 * ROWF)
#define SMEM_FLOATS (2 * GSTAGES * STAGEF)

template<int EPI>
__device__ __forceinline__ void gemm_load_stage(float* smemf, int slot, int kt,
                                                const float* __restrict__ A,
                                                const float* __restrict__ W,
                                                int m0, int n0, int K, int tid)
{
    float* As = smemf + slot * STAGEF;
    float* Bs = smemf + (GSTAGES + slot) * STAGEF;
    int k0 = kt * BK;
    const float* Ag = A + (size_t)m0 * K + k0;
    const float* Wg = W + (size_t)n0 * K + k0;
    #pragma unroll
    for (int i = 0; i < 4; i++) {
        int idx = tid + i * 256;
        int r = idx >> 3, c = (idx & 7) << 2;
        cp16(As + r * ROWF + c, Ag + (size_t)r * K + c);
    }
    #pragma unroll
    for (int i = 0; i < 4; i++) {
        int idx = tid + i * 256;
        int r = idx >> 3, c = (idx & 7) << 2;
        cp16(Bs + r * ROWF + c, Wg + (size_t)r * K + c);
    }
}

template<int EPI>
__global__ __launch_bounds__(256, 2) void tc_gemm(
    const float* __restrict__ A, const float* __restrict__ W,
    const float* __restrict__ bias, const float* __restrict__ res,
    float* __restrict__ C, int N, int K)
{
    extern __shared__ float smemf[];
    int tid  = threadIdx.x;
    int wid  = tid >> 5;
    int lane = tid & 31;
    int wm   = wid & 3;
    int wn   = wid >> 2;
    int m0   = blockIdx.y * BM;
    int n0   = blockIdx.x * BN;

    float acc[2][8][4];
    #pragma unroll
    for (int fm = 0; fm < 2; fm++)
        #pragma unroll
        for (int fn = 0; fn < 8; fn++)
            #pragma unroll
            for (int e = 0; e < 4; e++) acc[fm][fn][e] = 0.f;

    const int NK = K / BK;

    gemm_load_stage<EPI>(smemf, 0, 0, A, W, m0, n0, K, tid);
    asm volatile("cp.async.commit_group;" ::: "memory");
    gemm_load_stage<EPI>(smemf, 1, 1, A, W, m0, n0, K, tid);
    asm volatile("cp.async.commit_group;" ::: "memory");

    int lr = lane >> 2;
    int lc = lane & 3;

    for (int kt = 0; kt < NK; kt++) {
        int s = kt % GSTAGES;
        asm volatile("cp.async.wait_group 1;" ::: "memory");
        __syncthreads();

        int kn = kt + 2;
        if (kn < NK)
            gemm_load_stage<EPI>(smemf, kn % GSTAGES, kn, A, W, m0, n0, K, tid);
        asm volatile("cp.async.commit_group;" ::: "memory");

        const float* As = smemf + s * STAGEF;
        const float* Bs = smemf + (GSTAGES + s) * STAGEF;

        #pragma unroll
        for (int k = 0; k < BK; k += 8) {
            uint32_t a[2][4], b[8][2];
            #pragma unroll
            for (int fm = 0; fm < 2; fm++) {
                const float* ap = As + (wm * 32 + fm * 16 + lr) * ROWF + k + lc;
                a[fm][0] = __float_as_uint(ap[0]);
                a[fm][1] = __float_as_uint(ap[8 * ROWF]);
                a[fm][2] = __float_as_uint(ap[4]);
                a[fm][3] = __float_as_uint(ap[8 * ROWF + 4]);
            }
            #pragma unroll
            for (int fn = 0; fn < 8; fn++) {
                const float* bp = Bs + (wn * 64 + fn * 8 + lr) * ROWF + k + lc;
                b[fn][0] = __float_as_uint(bp[0]);
                b[fn][1] = __float_as_uint(bp[4]);
            }
            #pragma unroll
            for (int fm = 0; fm < 2; fm++)
                #pragma unroll
                for (int fn = 0; fn < 8; fn++)
                    mma_tf32(acc[fm][fn], a[fm], b[fn]);
        }
        __syncthreads();
    }

    #pragma unroll
    for (int fm = 0; fm < 2; fm++) {
        #pragma unroll
        for (int fn = 0; fn < 8; fn++) {
            int rowa = m0 + wm * 32 + fm * 16 + lr;
            int colg = n0 + wn * 64 + fn * 8 + 2 * lc;
            float bx = bias[colg], by = bias[colg + 1];
            #pragma unroll
            for (int half = 0; half < 2; half++) {
                int rr = rowa + half * 8;
                float vx = acc[fm][fn][half * 2 + 0] + bx;
                float vy = acc[fm][fn][half * 2 + 1] + by;
                if (EPI == 1) { vx = tf32r(gelu_exact(vx)); vy = tf32r(gelu_exact(vy)); }
                if (EPI == 2) {
                    const float2 rv = *(const float2*)&res[(size_t)rr * N + colg];
                    vx += rv.x; vy += rv.y;
                }
                *(float2*)&C[(size_t)rr * N + colg] = make_float2(vx, vy);
            }
        }
    }
}

// ---------------------------------------------------------------------------
// LayerNorm: one block per row (D=1024), 256 threads, tf32-rounded output.
// ---------------------------------------------------------------------------
__global__ void ln_kernel(const float* __restrict__ x, const float* __restrict__ g,
                          const float* __restrict__ beta, float* __restrict__ out)
{
    int row = blockIdx.x;
    int tid = threadIdx.x;
    const float4* xr = (const float4*)(x + (size_t)row * Dv);
    float4 v = xr[tid];
    float s  = v.x + v.y + v.z + v.w;
    float sq = v.x*v.x + v.y*v.y + v.z*v.z + v.w*v.w;
    #pragma unroll
    for (int o = 16; o > 0; o >>= 1) {
        s  += __shfl_xor_sync(0xffffffffu, s, o);
        sq += __shfl_xor_sync(0xffffffffu, sq, o);
    }
    __shared__ float rs[8], rq[8];
    __shared__ float smean, srstd;
    int w = tid >> 5;
    if ((tid & 31) == 0) { rs[w] = s; rq[w] = sq; }
    __syncthreads();
    if (tid == 0) {
        float ts = 0.f, tq = 0.f;
        #pragma unroll
        for (int i = 0; i < 8; i++) { ts += rs[i]; tq += rq[i]; }
        float mean = ts * (1.0f / Dv);
        float var  = tq * (1.0f / Dv) - mean * mean;
        smean = mean;
        srstd = rsqrtf(var + 1e-5f);
    }
    __syncthreads();
    float mean = smean, rstd = srstd;
    float4 gg = ((const float4*)g)[tid];
    float4 bb = ((const float4*)beta)[tid];
    float4 o4;
    o4.x = tf32r((v.x - mean) * rstd * gg.x + bb.x);
    o4.y = tf32r((v.y - mean) * rstd * gg.y + bb.y);
    o4.z = tf32r((v.z - mean) * rstd * gg.z + bb.z);
    o4.w = tf32r((v.w - mean) * rstd * gg.w + bb.w);
    ((float4*)(out + (size_t)row * Dv))[tid] = o4;
}

// ---------------------------------------------------------------------------
// Tensor-core flash attention, banded (causal + 10 lookahead).
// CTA = 128 queries x 1 head. 8 warps x 16 query rows. Key tiles of 64.
// ---------------------------------------------------------------------------
#define APAD 68
#define AQ_OFF 0
#define AK_OFF (128 * APAD)
#define AV_OFF (AK_OFF + 64 * APAD)
#define AP_OFF (AV_OFF + 64 * APAD)
#define ASMEM_FLOATS (AP_OFF + 128 * APAD)

__global__ __launch_bounds__(256, 1) void attn_tc_kernel(
    const float* __restrict__ qkv, const float* __restrict__ vt, float* __restrict__ o)
{
    extern __shared__ float sm[];
    float* Qs = sm + AQ_OFF;
    float* Ks = sm + AK_OFF;
    float* Vs = sm + AV_OFF;
    float* Ps = sm + AP_OFF;

    int tid  = threadIdx.x;
    int lane = tid & 31;
    int wq   = tid >> 5;
    int lr   = lane >> 2;
    int lc   = lane & 3;
    int qt   = 15 - blockIdx.x;
    int q0   = qt * 128;
    int h    = blockIdx.y;
    int b    = blockIdx.z;

    const float SCALE = 0.125f * 1.4426950408889634f;

    for (int i = tid; i < 128 * 16; i += 256) {
        int row = i >> 4;
        int c4  = (i & 15) << 2;
        float4 q = *(const float4*)&qkv[(size_t)(b * Tv + q0 + row) * 3072 + h * 64 + c4];
        float4 r;
        r.x = tf32r(q.x * SCALE); r.y = tf32r(q.y * SCALE);
        r.z = tf32r(q.z * SCALE); r.w = tf32r(q.w * SCALE);
        *(float4*)&Qs[row * APAD + c4] = r;
    }

    int r0  = wq * 16 + lr;
    int iq0 = q0 + r0;
    int iq1 = iq0 + 8;
    int lim0 = iq0 + WINDOWv;
    int lim1 = iq1 + WINDOWv;

    float m0 = -1e30f, m1 = -1e30f, l0 = 0.f, l1 = 0.f;
    float oacc[8][4];
    #pragma unroll
    for (int nf = 0; nf < 8; nf++)
        #pragma unroll
        for (int e = 0; e < 4; e++) oacc[nf][e] = 0.f;

    int kmax   = min(q0 + 128 + WINDOWv, Tv);
    int ntiles = (kmax + 63) >> 6;

    const float* vbase = vt + (size_t)((b * Hv + h) * 64) * Tv;

    for (int kt = 0; kt < ntiles; kt++) {
        int k0 = kt << 6;
        __syncthreads();
        for (int i = tid; i < 64 * 16; i += 256) {
            int row = i >> 4;
            int c4  = (i & 15) << 2;
            float4 kk = *(const float4*)&qkv[(size_t)(b * Tv + k0 + row) * 3072 + 1024 + h * 64 + c4];
            float4 r;
            r.x = tf32r(kk.x); r.y = tf32r(kk.y); r.z = tf32r(kk.z); r.w = tf32r(kk.w);
            *(float4*)&Ks[row * APAD + c4] = r;
            float4 vv = *(const float4*)&vbase[(size_t)row * Tv + k0 + c4];
            *(float4*)&Vs[row * APAD + c4] = vv;
        }
        __syncthreads();

        float sacc[8][4];
        #pragma unroll
        for (int jf = 0; jf < 8; jf++)
            #pragma unroll
            for (int e = 0; e < 4; e++) sacc[jf][e] = 0.f;

        #pragma unroll
        for (int kd = 0; kd < 64; kd += 8) {
            uint32_t a[4], bfr[8][2];
            const float* ap = Qs + r0 * APAD + kd + lc;
            a[0] = __float_as_uint(ap[0]);
            a[1] = __float_as_uint(ap[8 * APAD]);
            a[2] = __float_as_uint(ap[4]);
            a[3] = __float_as_uint(ap[8 * APAD + 4]);
            #pragma unroll
            for (int jf = 0; jf < 8; jf++) {
                const float* bp = Ks + (jf * 8 + lr) * APAD + kd + lc;
                bfr[jf][0] = __float_as_uint(bp[0]);
                bfr[jf][1] = __float_as_uint(bp[4]);
            }
            #pragma unroll
            for (int jf = 0; jf < 8; jf++)
                mma_tf32(sacc[jf], a, bfr[jf]);
        }

        int jbase = k0 + 2 * lc;
        float mx0 = -1e30f, mx1 = -1e30f;
        #pragma unroll
        for (int jf = 0; jf < 8; jf++) {
            int jA = jbase + jf * 8, jB = jA + 1;
            sacc[jf][0] = (jA <= lim0) ? sacc[jf][0] : -1e30f;
            sacc[jf][1] = (jB <= lim0) ? sacc[jf][1] : -1e30f;
            sacc[jf][2] = (jA <= lim1) ? sacc[jf][2] : -1e30f;
            sacc[jf][3] = (jB <= lim1) ? sacc[jf][3] : -1e30f;
            mx0 = fmaxf(mx0, fmaxf(sacc[jf][0], sacc[jf][1]));
            mx1 = fmaxf(mx1, fmaxf(sacc[jf][2], sacc[jf][3]));
        }
        mx0 = fmaxf(mx0, __shfl_xor_sync(0xffffffffu, mx0, 1));
        mx0 = fmaxf(mx0, __shfl_xor_sync(0xffffffffu, mx0, 2));
        mx1 = fmaxf(mx1, __shfl_xor_sync(0xffffffffu, mx1, 1));
        mx1 = fmaxf(mx1, __shfl_xor_sync(0xffffffffu, mx1, 2));

        float mn0 = fmaxf(m0, mx0), mn1 = fmaxf(m1, mx1);
        float corr0 = exp2f(m0 - mn0), corr1 = exp2f(m1 - mn1);

        float ps0 = 0.f, ps1 = 0.f;
        #pragma unroll
        for (int jf = 0; jf < 8; jf++) {
            float p00 = tf32r(exp2f(sacc[jf][0] - mn0));
            float p01 = tf32r(exp2f(sacc[jf][1] - mn0));
            float p10 = tf32r(exp2f(sacc[jf][2] - mn1));
            float p11 = tf32r(exp2f(sacc[jf][3] - mn1));
            ps0 += p00 + p01;
            ps1 += p10 + p11;
            *(float2*)&Ps[r0 * APAD + jf * 8 + 2 * lc]       = make_float2(p00, p01);
            *(float2*)&Ps[(r0 + 8) * APAD + jf * 8 + 2 * lc] = make_float2(p10, p11);
        }
        ps0 += __shfl_xor_sync(0xffffffffu, ps0, 1);
        ps0 += __shfl_xor_sync(0xffffffffu, ps0, 2);
        ps1 += __shfl_xor_sync(0xffffffffu, ps1, 1);
        ps1 += __shfl_xor_sync(0xffffffffu, ps1, 2);

        l0 = l0 * corr0 + ps0;
        l1 = l1 * corr1 + ps1;
        m0 = mn0; m1 = mn1;
        #pragma unroll
        for (int nf = 0; nf < 8; nf++) {
            oacc[nf][0] *= corr0; oacc[nf][1] *= corr0;
            oacc[nf][2] *= corr1; oacc[nf][3] *= corr1;
        }
        __syncwarp();

        #pragma unroll
        for (int kj = 0; kj < 64; kj += 8) {
            uint32_t a[4], bfr[8][2];
            const float* ap = Ps + r0 * APAD + kj + lc;
            a[0] = __float_as_uint(ap[0]);
            a[1] = __float_as_uint(ap[8 * APAD]);
            a[2] = __float_as_uint(ap[4]);
            a[3] = __float_as_uint(ap[8 * APAD + 4]);
            #pragma unroll
            for (int nf = 0; nf < 8; nf++) {
                const float* bp = Vs + (nf * 8 + lr) * APAD + kj + lc;
                bfr[nf][0] = __float_as_uint(bp[0]);
                bfr[nf][1] = __float_as_uint(bp[4]);
            }
            #pragma unroll
            for (int nf = 0; nf < 8; nf++)
                mma_tf32(oacc[nf], a, bfr[nf]);
        }
        __syncwarp();
    }

    float inv0 = 1.0f / l0, inv1 = 1.0f / l1;
    #pragma unroll
    for (int nf = 0; nf < 8; nf++) {
        int col = h * 64 + nf * 8 + 2 * lc;
        float2 v0 = make_float2(tf32r(oacc[nf][0] * inv0), tf32r(oacc[nf][1] * inv0));
        float2 v1 = make_float2(tf32r(oacc[nf][2] * inv1), tf32r(oacc[nf][3] * inv1));
        *(float2*)&o[(size_t)(b * Tv + iq0) * Dv + col] = v0;
        *(float2*)&o[(size_t)(b * Tv + iq1) * Dv + col] = v1;
    }
}

// ---------------------------------------------------------------------------
// Launch
// ---------------------------------------------------------------------------
extern "C" void kernel_launch(void* const* d_in, const int* in_sizes, int n_in,
                              void* d_out, int out_size)
{
    const float* x     = (const float*)d_in[0];
    const float* in_w  = (const float*)d_in[1];
    const float* in_b  = (const float*)d_in[2];
    const float* out_w = (const float*)d_in[3];
    const float* out_b = (const float*)d_in[4];
    const float* ln1g  = (const float*)d_in[5];
    const float* ln1b  = (const float*)d_in[6];
    const float* w1    = (const float*)d_in[7];
    const float* b1    = (const float*)d_in[8];
    const float* w2    = (const float*)d_in[9];
    const float* b2    = (const float*)d_in[10];
    const float* ln2g  = (const float*)d_in[11];
    const float* ln2b  = (const float*)d_in[12];
    float* out = (float*)d_out;

    float *h, *qkv, *o, *ff, *vt, *wqkv, *wout, *w1r, *w2r;
    cudaGetSymbolAddress((void**)&h,    g_h);
    cudaGetSymbolAddress((void**)&qkv,  g_qkv);
    cudaGetSymbolAddress((void**)&o,    g_o);
    cudaGetSymbolAddress((void**)&ff,   g_ff);
    cudaGetSymbolAddress((void**)&vt,   g_vt);
    cudaGetSymbolAddress((void**)&wqkv, g_wqkv);
    cudaGetSymbolAddress((void**)&wout, g_wout);
    cudaGetSymbolAddress((void**)&w1r,  g_w1r);
    cudaGetSymbolAddress((void**)&w2r,  g_w2r);

    const int SMEM_GEMM = SMEM_FLOATS * 4;         // 110592 B
    const int SMEM_ATTN = ASMEM_FLOATS * 4;        // 104448 B
    cudaFuncSetAttribute(attn_tc_kernel, cudaFuncAttributeMaxDynamicSharedMemorySize, SMEM_ATTN);
    cudaFuncSetAttribute(tc_gemm<0>, cudaFuncAttributeMaxDynamicSharedMemorySize, SMEM_GEMM);
    cudaFuncSetAttribute(tc_gemm<1>, cudaFuncAttributeMaxDynamicSharedMemorySize, SMEM_GEMM);
    cudaFuncSetAttribute(tc_gemm<2>, cudaFuncAttributeMaxDynamicSharedMemorySize, SMEM_GEMM);

    // 0) tf32-round all weights (single fused launch)
    round_all_kernel<<<592, 256>>>((const float4*)in_w,  (float4*)wqkv,
                                   (const float4*)out_w, (float4*)wout,
                                   (const float4*)w1,    (float4*)w1r,
                                   (const float4*)w2,    (float4*)w2r);

    // 1) h = LN1(x)  (tf32-rounded)
    ln_kernel<<<Mv, 256>>>(x, ln1g, ln1b, h);

    // 2) qkv = h @ in_proj_w^T + in_proj_b     [4096, 3072]
    tc_gemm<0><<<dim3(3072 / BN, Mv / BM), 256, SMEM_GEMM>>>(h, wqkv, in_b, nullptr, qkv, 3072, 1024);

    // 3a) V transpose: g_vt[b][h][d][t]
    vt_kernel<<<dim3(Tv / 32, Dv / 32, Bv), dim3(32, 8)>>>(qkv, vt);

    // 3b) o = tensor-core banded flash attention
    attn_tc_kernel<<<dim3(Tv / 128, Hv, Bv), 256, SMEM_ATTN>>>(qkv, vt, o);

    // 4) x1 = o @ out_w^T + out_b + x  -> d_out
    tc_gemm<2><<<dim3(1024 / BN, Mv / BM), 256, SMEM_GEMM>>>(o, wout, out_b, x, out, 1024, 1024);

    // 5) h2 = LN2(x1)  (tf32-rounded)
    ln_kernel<<<Mv, 256>>>(out, ln2g, ln2b, h);

    // 6) ff = GELU(h2 @ w1^T + b1)             [4096, 4096]
    tc_gemm<1><<<dim3(4096 / BN, Mv / BM), 256, SMEM_GEMM>>>(h, w1r, b1, nullptr, ff, 4096, 1024);

    // 7) out = ff @ w2^T + b2 + x1  (in-place residual on d_out)
    tc_gemm<2><<<dim3(1024 / BN, Mv / BM), 256, SMEM_GEMM>>>(ff, w2r, b2, out, out, 1024, 4096);
}

// round 7
// speedup vs baseline: 5.6769x; 1.8098x over previous
#include <cuda_runtime.h>
#include <cuda_fp16.h>
#include <math.h>
#include <cstdint>

// Problem constants
#define Bv 2
#define Tv 2048
#define Dv 1024
#define Hv 16
#define Mv 4096          // B*T
#define WINDOWv 10

// ---------------------------------------------------------------------------
// Scratch (static __device__ arrays; no allocation allowed)
// ---------------------------------------------------------------------------
__device__ __half g_h  [Mv * Dv];           // LN output (fp16)
__device__ __half g_qkv[Mv * 3 * Dv];       // QKV projection output (fp16)
__device__ __half g_o  [Mv * Dv];           // attention output (fp16)
__device__ __half g_ff [Mv * 4 * Dv];       // FFN hidden (fp16)
__device__ __half g_vt [Bv * Hv * 64 * Tv]; // V transposed: [b][h][d][t] (fp16)
__device__ __half g_wqkv[3 * Dv * Dv];      // fp16 weights
__device__ __half g_wout[Dv * Dv];
__device__ __half g_w1h [4 * Dv * Dv];
__device__ __half g_w2h [Dv * 4 * Dv];

// ---------------------------------------------------------------------------
// Helpers
// ---------------------------------------------------------------------------
__device__ __forceinline__ void cp16(void* dst, const void* src) {
    uint32_t d;
    asm("{ .reg .u64 t; cvta.to.shared.u64 t, %1; cvt.u32.u64 %0, t; }" : "=r"(d) : "l"(dst));
    asm volatile("cp.async.cg.shared.global [%0], [%1], 16;" :: "r"(d), "l"(src) : "memory");
}

__device__ __forceinline__ float gelu_exact(float x) {
    return 0.5f * x * (1.0f + erff(x * 0.70710678118654752f));
}

// m16n8k16 fp16 mma, fp32 accumulate
__device__ __forceinline__ void mma_f16(float* c, const uint32_t* a, const uint32_t* b) {
    asm volatile(
        "mma.sync.aligned.m16n8k16.row.col.f32.f16.f16.f32 "
        "{%0,%1,%2,%3}, {%4,%5,%6,%7}, {%8,%9}, {%0,%1,%2,%3};"
        : "+f"(c[0]), "+f"(c[1]), "+f"(c[2]), "+f"(c[3])
        : "r"(a[0]), "r"(a[1]), "r"(a[2]), "r"(a[3]), "r"(b[0]), "r"(b[1]));
}

// ---------------------------------------------------------------------------
// Fused weight fp16 conversion: all 4 weight matrices in one launch.
// ---------------------------------------------------------------------------
__global__ void round_all_kernel(const float4* __restrict__ i0, __half* __restrict__ o0,
                                 const float4* __restrict__ i1, __half* __restrict__ o1,
                                 const float4* __restrict__ i2, __half* __restrict__ o2,
                                 const float4* __restrict__ i3, __half* __restrict__ o3)
{
    const int n0 = 3 * Dv * Dv / 4;
    const int n1 = Dv * Dv / 4;
    const int n2 = 4 * Dv * Dv / 4;
    const int n3 = 4 * Dv * Dv / 4;
    const int total = n0 + n1 + n2 + n3;
    int stride = gridDim.x * blockDim.x;
    for (int i = blockIdx.x * blockDim.x + threadIdx.x; i < total; i += stride) {
        const float4* in; __half* out; int idx = i;
        if (idx < n0)                { in = i0; out = o0; }
        else if ((idx -= n0) < n1)   { in = i1; out = o1; }
        else if ((idx -= n1) < n2)   { in = i2; out = o2; }
        else { idx -= n2;              in = i3; out = o3; }
        float4 v = in[idx];
        __half2 h0 = __floats2half2_rn(v.x, v.y);
        __half2 h1 = __floats2half2_rn(v.z, v.w);
        uint2 pk;
        pk.x = *(uint32_t*)&h0;
        pk.y = *(uint32_t*)&h1;
        *(uint2*)&out[(size_t)idx * 4] = pk;
    }
}

// ---------------------------------------------------------------------------
// V transpose: g_vt[b][h][d][t] = qkv[b][t][2048 + h*64 + d]  (fp16)
// ---------------------------------------------------------------------------
__global__ void vt_kernel(const __half* __restrict__ qkv, __half* __restrict__ vt)
{
    __shared__ float tile[32][33];
    int t0  = blockIdx.x * 32;
    int dg0 = blockIdx.y * 32;
    int b   = blockIdx.z;
    int tx  = threadIdx.x, ty = threadIdx.y;
    #pragma unroll
    for (int i = 0; i < 4; i++) {
        int t = t0 + ty + i * 8;
        tile[ty + i * 8][tx] = __half2float(qkv[(size_t)(b * Tv + t) * 3072 + 2048 + dg0 + tx]);
    }
    __syncthreads();
    #pragma unroll
    for (int i = 0; i < 4; i++) {
        int dg = dg0 + ty + i * 8;
        int h = dg >> 6, d = dg & 63;
        vt[(size_t)((b * Hv + h) * 64 + d) * Tv + t0 + tx] = __float2half(tile[tx][ty + i * 8]);
    }
}

// ---------------------------------------------------------------------------
// fp16 mma.sync GEMM: C[M,N] = A[M,K] * W[N,K]^T + bias (+ epilogue)
//   EPI 0: bias -> half   EPI 1: bias + GELU -> half   EPI 2: bias + residual -> float
// CTA tile 128x128, BK=32, 8 warps (4 M x 2 N), warp tile 32x64.
// 4-stage cp.async pipeline; 2 CTAs/SM (2 x 80 KB smem).
// Smem rows padded to 40 halfs: fragment bank = (20*lr + lc) % 32, conflict-free.
// ---------------------------------------------------------------------------
#define BM 128
#define BN 128
#define BK 32
#define GSTAGES 4
#define ROWH 40
#define STAGEH (128 * ROWH)                 // 5120 halfs per stage
#define SMEM_HALFS (2 * GSTAGES * STAGEH)   // 40960 halfs = 81920 B

__device__ __forceinline__ void gemm_load_stage(__half* smemh, int slot, int kt,
                                                const __half* __restrict__ A,
                                                const __half* __restrict__ W,
                                                int m0, int n0, int K, int tid)
{
    __half* As = smemh + slot * STAGEH;
    __half* Bs = smemh + (GSTAGES + slot) * STAGEH;
    int k0 = kt * BK;
    const __half* Ag = A + (size_t)m0 * K + k0;
    const __half* Wg = W + (size_t)n0 * K + k0;
    // 128 rows x 32 halfs = 4 x 16B per row -> 512 cp16 each for A and B
    #pragma unroll
    for (int i = 0; i < 2; i++) {
        int idx = tid + i * 256;
        int r = idx >> 2, c = (idx & 3) << 3;   // c in halfs
        cp16(As + r * ROWH + c, Ag + (size_t)r * K + c);
    }
    #pragma unroll
    for (int i = 0; i < 2; i++) {
        int idx = tid + i * 256;
        int r = idx >> 2, c = (idx & 3) << 3;
        cp16(Bs + r * ROWH + c, Wg + (size_t)r * K + c);
    }
}

template<int EPI>
__global__ __launch_bounds__(256, 2) void tc_gemm(
    const __half* __restrict__ A, const __half* __restrict__ W,
    const float* __restrict__ bias, const float* __restrict__ res,
    void* __restrict__ Cv, int N, int K)
{
    extern __shared__ __half smemh[];
    int tid  = threadIdx.x;
    int wid  = tid >> 5;
    int lane = tid & 31;
    int wm   = wid & 3;
    int wn   = wid >> 2;
    int m0   = blockIdx.y * BM;
    int n0   = blockIdx.x * BN;

    float acc[2][8][4];
    #pragma unroll
    for (int fm = 0; fm < 2; fm++)
        #pragma unroll
        for (int fn = 0; fn < 8; fn++)
            #pragma unroll
            for (int e = 0; e < 4; e++) acc[fm][fn][e] = 0.f;

    const int NK = K / BK;

    gemm_load_stage(smemh, 0, 0, A, W, m0, n0, K, tid);
    asm volatile("cp.async.commit_group;" ::: "memory");
    gemm_load_stage(smemh, 1, 1, A, W, m0, n0, K, tid);
    asm volatile("cp.async.commit_group;" ::: "memory");
    gemm_load_stage(smemh, 2, 2, A, W, m0, n0, K, tid);
    asm volatile("cp.async.commit_group;" ::: "memory");

    int lr = lane >> 2;
    int lc = lane & 3;

    for (int kt = 0; kt < NK; kt++) {
        int s = kt & (GSTAGES - 1);
        asm volatile("cp.async.wait_group 2;" ::: "memory");
        __syncthreads();

        // Refill stage kt+3 into slot (kt+3)%4 == (kt-1)%4 (compute done last iter).
        int kn = kt + 3;
        if (kn < NK)
            gemm_load_stage(smemh, kn & (GSTAGES - 1), kn, A, W, m0, n0, K, tid);
        asm volatile("cp.async.commit_group;" ::: "memory");

        const __half* As = smemh + s * STAGEH;
        const __half* Bs = smemh + (GSTAGES + s) * STAGEH;

        #pragma unroll
        for (int k = 0; k < BK; k += 16) {
            uint32_t a[2][4], b[8][2];
            #pragma unroll
            for (int fm = 0; fm < 2; fm++) {
                const __half* ap = As + (wm * 32 + fm * 16 + lr) * ROWH + k + 2 * lc;
                a[fm][0] = *(const uint32_t*)&ap[0];
                a[fm][1] = *(const uint32_t*)&ap[8 * ROWH];
                a[fm][2] = *(const uint32_t*)&ap[8];
                a[fm][3] = *(const uint32_t*)&ap[8 * ROWH + 8];
            }
            #pragma unroll
            for (int fn = 0; fn < 8; fn++) {
                const __half* bp = Bs + (wn * 64 + fn * 8 + lr) * ROWH + k + 2 * lc;
                b[fn][0] = *(const uint32_t*)&bp[0];
                b[fn][1] = *(const uint32_t*)&bp[8];
            }
            #pragma unroll
            for (int fm = 0; fm < 2; fm++)
                #pragma unroll
                for (int fn = 0; fn < 8; fn++)
                    mma_f16(acc[fm][fn], a[fm], b[fn]);
        }
        __syncthreads();
    }

    #pragma unroll
    for (int fm = 0; fm < 2; fm++) {
        #pragma unroll
        for (int fn = 0; fn < 8; fn++) {
            int rowa = m0 + wm * 32 + fm * 16 + lr;
            int colg = n0 + wn * 64 + fn * 8 + 2 * lc;
            float bx = bias[colg], by = bias[colg + 1];
            #pragma unroll
            for (int half_i = 0; half_i < 2; half_i++) {
                int rr = rowa + half_i * 8;
                float vx = acc[fm][fn][half_i * 2 + 0] + bx;
                float vy = acc[fm][fn][half_i * 2 + 1] + by;
                if (EPI == 1) { vx = gelu_exact(vx); vy = gelu_exact(vy); }
                if (EPI == 2) {
                    const float2 rv = *(const float2*)&res[(size_t)rr * N + colg];
                    vx += rv.x; vy += rv.y;
                    *(float2*)&((float*)Cv)[(size_t)rr * N + colg] = make_float2(vx, vy);
                } else {
                    __half2 hv = __floats2half2_rn(vx, vy);
                    *(__half2*)&((__half*)Cv)[(size_t)rr * N + colg] = hv;
                }
            }
        }
    }
}

// ---------------------------------------------------------------------------
// LayerNorm: one block per row (D=1024), 256 threads, fp16 output.
// ---------------------------------------------------------------------------
__global__ void ln_kernel(const float* __restrict__ x, const float* __restrict__ g,
                          const float* __restrict__ beta, __half* __restrict__ out)
{
    int row = blockIdx.x;
    int tid = threadIdx.x;
    const float4* xr = (const float4*)(x + (size_t)row * Dv);
    float4 v = xr[tid];
    float s  = v.x + v.y + v.z + v.w;
    float sq = v.x*v.x + v.y*v.y + v.z*v.z + v.w*v.w;
    #pragma unroll
    for (int o = 16; o > 0; o >>= 1) {
        s  += __shfl_xor_sync(0xffffffffu, s, o);
        sq += __shfl_xor_sync(0xffffffffu, sq, o);
    }
    __shared__ float rs[8], rq[8];
    __shared__ float smean, srstd;
    int w = tid >> 5;
    if ((tid & 31) == 0) { rs[w] = s; rq[w] = sq; }
    __syncthreads();
    if (tid == 0) {
        float ts = 0.f, tq = 0.f;
        #pragma unroll
        for (int i = 0; i < 8; i++) { ts += rs[i]; tq += rq[i]; }
        float mean = ts * (1.0f / Dv);
        float var  = tq * (1.0f / Dv) - mean * mean;
        smean = mean;
        srstd = rsqrtf(var + 1e-5f);
    }
    __syncthreads();
    float mean = smean, rstd = srstd;
    float4 gg = ((const float4*)g)[tid];
    float4 bb = ((const float4*)beta)[tid];
    __half2 h0 = __floats2half2_rn((v.x - mean) * rstd * gg.x + bb.x,
                                   (v.y - mean) * rstd * gg.y + bb.y);
    __half2 h1 = __floats2half2_rn((v.z - mean) * rstd * gg.z + bb.z,
                                   (v.w - mean) * rstd * gg.w + bb.w);
    uint2 pk;
    pk.x = *(uint32_t*)&h0;
    pk.y = *(uint32_t*)&h1;
    *(uint2*)&out[(size_t)row * Dv + 4 * tid] = pk;
}

// ---------------------------------------------------------------------------
// fp16 tensor-core flash attention, banded (causal + 10 lookahead).
// CTA = 128 queries x 1 head. 8 warps x 16 query rows. Key tiles of 64.
// Smem (halfs, pad 72): Qs[128][72] Ks[64][72] Vs[64][72] Ps[128][72].
// ---------------------------------------------------------------------------
#define APADH 72
#define AQ_OFF 0
#define AK_OFF (128 * APADH)
#define AV_OFF (AK_OFF + 64 * APADH)
#define AP_OFF (AV_OFF + 64 * APADH)
#define ASMEM_HALFS (AP_OFF + 128 * APADH)   // 27648 halfs = 55296 B

__global__ __launch_bounds__(256, 2) void attn_tc_kernel(
    const __half* __restrict__ qkv, const __half* __restrict__ vt, __half* __restrict__ o)
{
    extern __shared__ __half smh[];
    __half* Qs = smh + AQ_OFF;
    __half* Ks = smh + AK_OFF;
    __half* Vs = smh + AV_OFF;
    __half* Ps = smh + AP_OFF;

    int tid  = threadIdx.x;
    int lane = tid & 31;
    int wq   = tid >> 5;
    int lr   = lane >> 2;
    int lc   = lane & 3;
    int qt   = 15 - blockIdx.x;
    int q0   = qt * 128;
    int h    = blockIdx.y;
    int b    = blockIdx.z;

    const float SCALE = 0.125f * 1.4426950408889634f;
    const __half2 s2 = __floats2half2_rn(SCALE, SCALE);

    // Load + scale Q tile (128 rows x 64 halfs, 16B chunks)
    for (int i = tid; i < 128 * 8; i += 256) {
        int row = i >> 3;
        int c8  = (i & 7) << 3;
        uint4 v = *(const uint4*)&qkv[(size_t)(b * Tv + q0 + row) * 3072 + h * 64 + c8];
        __half2* p = (__half2*)&v;
        p[0] = __hmul2(p[0], s2); p[1] = __hmul2(p[1], s2);
        p[2] = __hmul2(p[2], s2); p[3] = __hmul2(p[3], s2);
        *(uint4*)&Qs[row * APADH + c8] = v;
    }

    int r0  = wq * 16 + lr;
    int iq0 = q0 + r0;
    int iq1 = iq0 + 8;
    int lim0 = iq0 + WINDOWv;
    int lim1 = iq1 + WINDOWv;

    float m0 = -1e30f, m1 = -1e30f, l0 = 0.f, l1 = 0.f;
    float oacc[8][4];
    #pragma unroll
    for (int nf = 0; nf < 8; nf++)
        #pragma unroll
        for (int e = 0; e < 4; e++) oacc[nf][e] = 0.f;

    int kmax   = min(q0 + 128 + WINDOWv, Tv);
    int ntiles = (kmax + 63) >> 6;

    const __half* vbase = vt + (size_t)((b * Hv + h) * 64) * Tv;

    for (int kt = 0; kt < ntiles; kt++) {
        int k0 = kt << 6;
        __syncthreads();
        // Copy K tile [j][d] and V^T tile [d][j] (pure 16B copies)
        for (int i = tid; i < 64 * 8; i += 256) {
            int row = i >> 3;
            int c8  = (i & 7) << 3;
            *(uint4*)&Ks[row * APADH + c8] =
                *(const uint4*)&qkv[(size_t)(b * Tv + k0 + row) * 3072 + 1024 + h * 64 + c8];
            *(uint4*)&Vs[row * APADH + c8] =
                *(const uint4*)&vbase[(size_t)row * Tv + k0 + c8];
        }
        __syncthreads();

        // S = Q K^T
        float sacc[8][4];
        #pragma unroll
        for (int jf = 0; jf < 8; jf++)
            #pragma unroll
            for (int e = 0; e < 4; e++) sacc[jf][e] = 0.f;

        #pragma unroll
        for (int kd = 0; kd < 64; kd += 16) {
            uint32_t a[4], bfr[8][2];
            const __half* ap = Qs + r0 * APADH + kd + 2 * lc;
            a[0] = *(const uint32_t*)&ap[0];
            a[1] = *(const uint32_t*)&ap[8 * APADH];
            a[2] = *(const uint32_t*)&ap[8];
            a[3] = *(const uint32_t*)&ap[8 * APADH + 8];
            #pragma unroll
            for (int jf = 0; jf < 8; jf++) {
                const __half* bp = Ks + (jf * 8 + lr) * APADH + kd + 2 * lc;
                bfr[jf][0] = *(const uint32_t*)&bp[0];
                bfr[jf][1] = *(const uint32_t*)&bp[8];
            }
            #pragma unroll
            for (int jf = 0; jf < 8; jf++)
                mma_f16(sacc[jf], a, bfr[jf]);
        }

        // Mask + row max (rows r0, r0+8)
        int jbase = k0 + 2 * lc;
        float mx0 = -1e30f, mx1 = -1e30f;
        #pragma unroll
        for (int jf = 0; jf < 8; jf++) {
            int jA = jbase + jf * 8, jB = jA + 1;
            sacc[jf][0] = (jA <= lim0) ? sacc[jf][0] : -1e30f;
            sacc[jf][1] = (jB <= lim0) ? sacc[jf][1] : -1e30f;
            sacc[jf][2] = (jA <= lim1) ? sacc[jf][2] : -1e30f;
            sacc[jf][3] = (jB <= lim1) ? sacc[jf][3] : -1e30f;
            mx0 = fmaxf(mx0, fmaxf(sacc[jf][0], sacc[jf][1]));
            mx1 = fmaxf(mx1, fmaxf(sacc[jf][2], sacc[jf][3]));
        }
        mx0 = fmaxf(mx0, __shfl_xor_sync(0xffffffffu, mx0, 1));
        mx0 = fmaxf(mx0, __shfl_xor_sync(0xffffffffu, mx0, 2));
        mx1 = fmaxf(mx1, __shfl_xor_sync(0xffffffffu, mx1, 1));
        mx1 = fmaxf(mx1, __shfl_xor_sync(0xffffffffu, mx1, 2));

        float mn0 = fmaxf(m0, mx0), mn1 = fmaxf(m1, mx1);
        float corr0 = exp2f(m0 - mn0), corr1 = exp2f(m1 - mn1);

        float ps0 = 0.f, ps1 = 0.f;
        #pragma unroll
        for (int jf = 0; jf < 8; jf++) {
            float p00 = exp2f(sacc[jf][0] - mn0);
            float p01 = exp2f(sacc[jf][1] - mn0);
            float p10 = exp2f(sacc[jf][2] - mn1);
            float p11 = exp2f(sacc[jf][3] - mn1);
            ps0 += p00 + p01;
            ps1 += p10 + p11;
            *(__half2*)&Ps[r0 * APADH + jf * 8 + 2 * lc]       = __floats2half2_rn(p00, p01);
            *(__half2*)&Ps[(r0 + 8) * APADH + jf * 8 + 2 * lc] = __floats2half2_rn(p10, p11);
        }
        ps0 += __shfl_xor_sync(0xffffffffu, ps0, 1);
        ps0 += __shfl_xor_sync(0xffffffffu, ps0, 2);
        ps1 += __shfl_xor_sync(0xffffffffu, ps1, 1);
        ps1 += __shfl_xor_sync(0xffffffffu, ps1, 2);

        l0 = l0 * corr0 + ps0;
        l1 = l1 * corr1 + ps1;
        m0 = mn0; m1 = mn1;
        #pragma unroll
        for (int nf = 0; nf < 8; nf++) {
            oacc[nf][0] *= corr0; oacc[nf][1] *= corr0;
            oacc[nf][2] *= corr1; oacc[nf][3] *= corr1;
        }
        __syncwarp();

        // O += P V   (A = P from smem, B = V^T tile)
        #pragma unroll
        for (int kj = 0; kj < 64; kj += 16) {
            uint32_t a[4], bfr[8][2];
            const __half* ap = Ps + r0 * APADH + kj + 2 * lc;
            a[0] = *(const uint32_t*)&ap[0];
            a[1] = *(const uint32_t*)&ap[8 * APADH];
            a[2] = *(const uint32_t*)&ap[8];
            a[3] = *(const uint32_t*)&ap[8 * APADH + 8];
            #pragma unroll
            for (int nf = 0; nf < 8; nf++) {
                const __half* bp = Vs + (nf * 8 + lr) * APADH + kj + 2 * lc;
                bfr[nf][0] = *(const uint32_t*)&bp[0];
                bfr[nf][1] = *(const uint32_t*)&bp[8];
            }
            #pragma unroll
            for (int nf = 0; nf < 8; nf++)
                mma_f16(oacc[nf], a, bfr[nf]);
        }
        __syncwarp();
    }

    // Normalize and store (fp16; feeds out-proj GEMM)
    float inv0 = 1.0f / l0, inv1 = 1.0f / l1;
    #pragma unroll
    for (int nf = 0; nf < 8; nf++) {
        int col = h * 64 + nf * 8 + 2 * lc;
        *(__half2*)&o[(size_t)(b * Tv + iq0) * Dv + col] =
            __floats2half2_rn(oacc[nf][0] * inv0, oacc[nf][1] * inv0);
        *(__half2*)&o[(size_t)(b * Tv + iq1) * Dv + col] =
            __floats2half2_rn(oacc[nf][2] * inv1, oacc[nf][3] * inv1);
    }
}

// ---------------------------------------------------------------------------
// Launch
// ---------------------------------------------------------------------------
extern "C" void kernel_launch(void* const* d_in, const int* in_sizes, int n_in,
                              void* d_out, int out_size)
{
    const float* x     = (const float*)d_in[0];
    const float* in_w  = (const float*)d_in[1];
    const float* in_b  = (const float*)d_in[2];
    const float* out_w = (const float*)d_in[3];
    const float* out_b = (const float*)d_in[4];
    const float* ln1g  = (const float*)d_in[5];
    const float* ln1b  = (const float*)d_in[6];
    const float* w1    = (const float*)d_in[7];
    const float* b1    = (const float*)d_in[8];
    const float* w2    = (const float*)d_in[9];
    const float* b2    = (const float*)d_in[10];
    const float* ln2g  = (const float*)d_in[11];
    const float* ln2b  = (const float*)d_in[12];
    float* out = (float*)d_out;

    __half *h, *qkv, *o, *ff, *vt, *wqkv, *wout, *w1h, *w2h;
    cudaGetSymbolAddress((void**)&h,    g_h);
    cudaGetSymbolAddress((void**)&qkv,  g_qkv);
    cudaGetSymbolAddress((void**)&o,    g_o);
    cudaGetSymbolAddress((void**)&ff,   g_ff);
    cudaGetSymbolAddress((void**)&vt,   g_vt);
    cudaGetSymbolAddress((void**)&wqkv, g_wqkv);
    cudaGetSymbolAddress((void**)&wout, g_wout);
    cudaGetSymbolAddress((void**)&w1h,  g_w1h);
    cudaGetSymbolAddress((void**)&w2h,  g_w2h);

    const int SMEM_GEMM = SMEM_HALFS * 2;    // 81920 B
    const int SMEM_ATTN = ASMEM_HALFS * 2;   // 55296 B
    cudaFuncSetAttribute(attn_tc_kernel, cudaFuncAttributeMaxDynamicSharedMemorySize, SMEM_ATTN);
    cudaFuncSetAttribute(tc_gemm<0>, cudaFuncAttributeMaxDynamicSharedMemorySize, SMEM_GEMM);
    cudaFuncSetAttribute(tc_gemm<1>, cudaFuncAttributeMaxDynamicSharedMemorySize, SMEM_GEMM);
    cudaFuncSetAttribute(tc_gemm<2>, cudaFuncAttributeMaxDynamicSharedMemorySize, SMEM_GEMM);

    // 0) fp16-convert all weights (single fused launch)
    round_all_kernel<<<592, 256>>>((const float4*)in_w,  wqkv,
                                   (const float4*)out_w, wout,
                                   (const float4*)w1,    w1h,
                                   (const float4*)w2,    w2h);

    // 1) h = LN1(x)  (fp16)
    ln_kernel<<<Mv, 256>>>(x, ln1g, ln1b, h);

    // 2) qkv = h @ in_proj_w^T + in_proj_b     [4096, 3072] (fp16 out)
    tc_gemm<0><<<dim3(3072 / BN, Mv / BM), 256, SMEM_GEMM>>>(h, wqkv, in_b, nullptr, qkv, 3072, 1024);

    // 3a) V transpose: g_vt[b][h][d][t]
    vt_kernel<<<dim3(Tv / 32, Dv / 32, Bv), dim3(32, 8)>>>(qkv, vt);

    // 3b) o = fp16 tensor-core banded flash attention
    attn_tc_kernel<<<dim3(Tv / 128, Hv, Bv), 256, SMEM_ATTN>>>(qkv, vt, o);

    // 4) x1 = o @ out_w^T + out_b + x  -> d_out (fp32)
    tc_gemm<2><<<dim3(1024 / BN, Mv / BM), 256, SMEM_GEMM>>>(o, wout, out_b, x, out, 1024, 1024);

    // 5) h2 = LN2(x1)  (fp16)
    ln_kernel<<<Mv, 256>>>(out, ln2g, ln2b, h);

    // 6) ff = GELU(h2 @ w1^T + b1)             [4096, 4096] (fp16 out)
    tc_gemm<1><<<dim3(4096 / BN, Mv / BM), 256, SMEM_GEMM>>>(h, w1h, b1, nullptr, ff, 4096, 1024);

    // 7) out = ff @ w2^T + b2 + x1  (in-place residual on d_out, fp32)
    tc_gemm<2><<<dim3(1024 / BN, Mv / BM), 256, SMEM_GEMM>>>(ff, w2h, b2, out, out, 1024, 4096);
}

// round 8
// speedup vs baseline: 5.6972x; 1.0036x over previous
#include <cuda_runtime.h>
#include <cuda_fp16.h>
#include <math.h>
#include <cstdint>

// Problem constants
#define Bv 2
#define Tv 2048
#define Dv 1024
#define Hv 16
#define Mv 4096          // B*T
#define WINDOWv 10

// ---------------------------------------------------------------------------
// Scratch (static __device__ arrays; no allocation allowed)
// ---------------------------------------------------------------------------
__device__ __half g_h  [Mv * Dv];           // LN output (fp16)
__device__ __half g_qkv[Mv * 3 * Dv];       // QKV projection output (fp16)
__device__ __half g_o  [Mv * Dv];           // attention output (fp16)
__device__ __half g_ff [Mv * 4 * Dv];       // FFN hidden (fp16)
__device__ __half g_vt [Bv * Hv * 64 * Tv]; // V transposed: [b][h][d][t] (fp16)
__device__ __half g_wqkv[3 * Dv * Dv];      // fp16 weights
__device__ __half g_wout[Dv * Dv];
__device__ __half g_w1h [4 * Dv * Dv];
__device__ __half g_w2h [Dv * 4 * Dv];

// ---------------------------------------------------------------------------
// Helpers
// ---------------------------------------------------------------------------
__device__ __forceinline__ void cp16(void* dst, const void* src) {
    uint32_t d;
    asm("{ .reg .u64 t; cvta.to.shared.u64 t, %1; cvt.u32.u64 %0, t; }" : "=r"(d) : "l"(dst));
    asm volatile("cp.async.cg.shared.global [%0], [%1], 16;" :: "r"(d), "l"(src) : "memory");
}

__device__ __forceinline__ float gelu_exact(float x) {
    return 0.5f * x * (1.0f + erff(x * 0.70710678118654752f));
}

// m16n8k16 fp16 mma, fp32 accumulate
__device__ __forceinline__ void mma_f16(float* c, const uint32_t* a, const uint32_t* b) {
    asm volatile(
        "mma.sync.aligned.m16n8k16.row.col.f32.f16.f16.f32 "
        "{%0,%1,%2,%3}, {%4,%5,%6,%7}, {%8,%9}, {%0,%1,%2,%3};"
        : "+f"(c[0]), "+f"(c[1]), "+f"(c[2]), "+f"(c[3])
        : "r"(a[0]), "r"(a[1]), "r"(a[2]), "r"(a[3]), "r"(b[0]), "r"(b[1]));
}

// ---------------------------------------------------------------------------
// Fused weight fp16 conversion: all 4 weight matrices in one launch.
// ---------------------------------------------------------------------------
__global__ void round_all_kernel(const float4* __restrict__ i0, __half* __restrict__ o0,
                                 const float4* __restrict__ i1, __half* __restrict__ o1,
                                 const float4* __restrict__ i2, __half* __restrict__ o2,
                                 const float4* __restrict__ i3, __half* __restrict__ o3)
{
    const int n0 = 3 * Dv * Dv / 4;
    const int n1 = Dv * Dv / 4;
    const int n2 = 4 * Dv * Dv / 4;
    const int n3 = 4 * Dv * Dv / 4;
    const int total = n0 + n1 + n2 + n3;
    int stride = gridDim.x * blockDim.x;
    for (int i = blockIdx.x * blockDim.x + threadIdx.x; i < total; i += stride) {
        const float4* in; __half* out; int idx = i;
        if (idx < n0)                { in = i0; out = o0; }
        else if ((idx -= n0) < n1)   { in = i1; out = o1; }
        else if ((idx -= n1) < n2)   { in = i2; out = o2; }
        else { idx -= n2;              in = i3; out = o3; }
        float4 v = in[idx];
        __half2 h0 = __floats2half2_rn(v.x, v.y);
        __half2 h1 = __floats2half2_rn(v.z, v.w);
        uint2 pk;
        pk.x = *(uint32_t*)&h0;
        pk.y = *(uint32_t*)&h1;
        *(uint2*)&out[(size_t)idx * 4] = pk;
    }
}

// ---------------------------------------------------------------------------
// V transpose: g_vt[b][h][d][t] = qkv[b][t][2048 + h*64 + d]  (fp16)
// ---------------------------------------------------------------------------
__global__ void vt_kernel(const __half* __restrict__ qkv, __half* __restrict__ vt)
{
    __shared__ float tile[32][33];
    int t0  = blockIdx.x * 32;
    int dg0 = blockIdx.y * 32;
    int b   = blockIdx.z;
    int tx  = threadIdx.x, ty = threadIdx.y;
    #pragma unroll
    for (int i = 0; i < 4; i++) {
        int t = t0 + ty + i * 8;
        tile[ty + i * 8][tx] = __half2float(qkv[(size_t)(b * Tv + t) * 3072 + 2048 + dg0 + tx]);
    }
    __syncthreads();
    #pragma unroll
    for (int i = 0; i < 4; i++) {
        int dg = dg0 + ty + i * 8;
        int h = dg >> 6, d = dg & 63;
        vt[(size_t)((b * Hv + h) * 64 + d) * Tv + t0 + tx] = __float2half(tile[tx][ty + i * 8]);
    }
}

// ---------------------------------------------------------------------------
// fp16 mma.sync GEMM: C[M,N] = A[M,K] * W[N,K]^T + bias (+ epilogue)
//   EPI 0: bias -> half   EPI 1: bias + GELU -> half   EPI 2: bias + residual -> float
// CTA tile 128x128, BK=32, 8 warps (4 M x 2 N), warp tile 32x64.
// 4-stage cp.async pipeline; 2 CTAs/SM (2 x 80 KB smem).
// Smem rows padded to 40 halfs: fragment bank = (20*lr + lc) % 32, conflict-free.
// ---------------------------------------------------------------------------
#define BM 128
#define BN 128
#define BK 32
#define GSTAGES 4
#define ROWH 40
#define STAGEH (128 * ROWH)                 // 5120 halfs per stage
#define SMEM_HALFS (2 * GSTAGES * STAGEH)   // 40960 halfs = 81920 B

__device__ __forceinline__ void gemm_load_stage(__half* smemh, int slot, int kt,
                                                const __half* __restrict__ A,
                                                const __half* __restrict__ W,
                                                int m0, int n0, int K, int tid)
{
    __half* As = smemh + slot * STAGEH;
    __half* Bs = smemh + (GSTAGES + slot) * STAGEH;
    int k0 = kt * BK;
    const __half* Ag = A + (size_t)m0 * K + k0;
    const __half* Wg = W + (size_t)n0 * K + k0;
    // 128 rows x 32 halfs = 4 x 16B per row -> 512 cp16 each for A and B
    #pragma unroll
    for (int i = 0; i < 2; i++) {
        int idx = tid + i * 256;
        int r = idx >> 2, c = (idx & 3) << 3;   // c in halfs
        cp16(As + r * ROWH + c, Ag + (size_t)r * K + c);
    }
    #pragma unroll
    for (int i = 0; i < 2; i++) {
        int idx = tid + i * 256;
        int r = idx >> 2, c = (idx & 3) << 3;
        cp16(Bs + r * ROWH + c, Wg + (size_t)r * K + c);
    }
}

template<int EPI>
__global__ __launch_bounds__(256, 2) void tc_gemm(
    const __half* __restrict__ A, const __half* __restrict__ W,
    const float* __restrict__ bias, const float* __restrict__ res,
    void* __restrict__ Cv, int N, int K)
{
    extern __shared__ __half smemh[];
    int tid  = threadIdx.x;
    int wid  = tid >> 5;
    int lane = tid & 31;
    int wm   = wid & 3;
    int wn   = wid >> 2;
    int m0   = blockIdx.y * BM;
    int n0   = blockIdx.x * BN;

    float acc[2][8][4];
    #pragma unroll
    for (int fm = 0; fm < 2; fm++)
        #pragma unroll
        for (int fn = 0; fn < 8; fn++)
            #pragma unroll
            for (int e = 0; e < 4; e++) acc[fm][fn][e] = 0.f;

    const int NK = K / BK;

    gemm_load_stage(smemh, 0, 0, A, W, m0, n0, K, tid);
    asm volatile("cp.async.commit_group;" ::: "memory");
    gemm_load_stage(smemh, 1, 1, A, W, m0, n0, K, tid);
    asm volatile("cp.async.commit_group;" ::: "memory");
    gemm_load_stage(smemh, 2, 2, A, W, m0, n0, K, tid);
    asm volatile("cp.async.commit_group;" ::: "memory");

    int lr = lane >> 2;
    int lc = lane & 3;

    for (int kt = 0; kt < NK; kt++) {
        int s = kt & (GSTAGES - 1);
        asm volatile("cp.async.wait_group 2;" ::: "memory");
        __syncthreads();

        // Refill stage kt+3 into slot (kt+3)%4 == (kt-1)%4 (compute done last iter).
        int kn = kt + 3;
        if (kn < NK)
            gemm_load_stage(smemh, kn & (GSTAGES - 1), kn, A, W, m0, n0, K, tid);
        asm volatile("cp.async.commit_group;" ::: "memory");

        const __half* As = smemh + s * STAGEH;
        const __half* Bs = smemh + (GSTAGES + s) * STAGEH;

        #pragma unroll
        for (int k = 0; k < BK; k += 16) {
            uint32_t a[2][4], b[8][2];
            #pragma unroll
            for (int fm = 0; fm < 2; fm++) {
                const __half* ap = As + (wm * 32 + fm * 16 + lr) * ROWH + k + 2 * lc;
                a[fm][0] = *(const uint32_t*)&ap[0];
                a[fm][1] = *(const uint32_t*)&ap[8 * ROWH];
                a[fm][2] = *(const uint32_t*)&ap[8];
                a[fm][3] = *(const uint32_t*)&ap[8 * ROWH + 8];
            }
            #pragma unroll
            for (int fn = 0; fn < 8; fn++) {
                const __half* bp = Bs + (wn * 64 + fn * 8 + lr) * ROWH + k + 2 * lc;
                b[fn][0] = *(const uint32_t*)&bp[0];
                b[fn][1] = *(const uint32_t*)&bp[8];
            }
            #pragma unroll
            for (int fm = 0; fm < 2; fm++)
                #pragma unroll
                for (int fn = 0; fn < 8; fn++)
                    mma_f16(acc[fm][fn], a[fm], b[fn]);
        }
        __syncthreads();
    }

    #pragma unroll
    for (int fm = 0; fm < 2; fm++) {
        #pragma unroll
        for (int fn = 0; fn < 8; fn++) {
            int rowa = m0 + wm * 32 + fm * 16 + lr;
            int colg = n0 + wn * 64 + fn * 8 + 2 * lc;
            float bx = bias[colg], by = bias[colg + 1];
            #pragma unroll
            for (int half_i = 0; half_i < 2; half_i++) {
                int rr = rowa + half_i * 8;
                float vx = acc[fm][fn][half_i * 2 + 0] + bx;
                float vy = acc[fm][fn][half_i * 2 + 1] + by;
                if (EPI == 1) { vx = gelu_exact(vx); vy = gelu_exact(vy); }
                if (EPI == 2) {
                    const float2 rv = *(const float2*)&res[(size_t)rr * N + colg];
                    vx += rv.x; vy += rv.y;
                    *(float2*)&((float*)Cv)[(size_t)rr * N + colg] = make_float2(vx, vy);
                } else {
                    __half2 hv = __floats2half2_rn(vx, vy);
                    *(__half2*)&((__half*)Cv)[(size_t)rr * N + colg] = hv;
                }
            }
        }
    }
}

// ---------------------------------------------------------------------------
// LayerNorm: one block per row (D=1024), 256 threads, fp16 output.
// ---------------------------------------------------------------------------
__global__ void ln_kernel(const float* __restrict__ x, const float* __restrict__ g,
                          const float* __restrict__ beta, __half* __restrict__ out)
{
    int row = blockIdx.x;
    int tid = threadIdx.x;
    const float4* xr = (const float4*)(x + (size_t)row * Dv);
    float4 v = xr[tid];
    float s  = v.x + v.y + v.z + v.w;
    float sq = v.x*v.x + v.y*v.y + v.z*v.z + v.w*v.w;
    #pragma unroll
    for (int o = 16; o > 0; o >>= 1) {
        s  += __shfl_xor_sync(0xffffffffu, s, o);
        sq += __shfl_xor_sync(0xffffffffu, sq, o);
    }
    __shared__ float rs[8], rq[8];
    __shared__ float smean, srstd;
    int w = tid >> 5;
    if ((tid & 31) == 0) { rs[w] = s; rq[w] = sq; }
    __syncthreads();
    if (tid == 0) {
        float ts = 0.f, tq = 0.f;
        #pragma unroll
        for (int i = 0; i < 8; i++) { ts += rs[i]; tq += rq[i]; }
        float mean = ts * (1.0f / Dv);
        float var  = tq * (1.0f / Dv) - mean * mean;
        smean = mean;
        srstd = rsqrtf(var + 1e-5f);
    }
    __syncthreads();
    float mean = smean, rstd = srstd;
    float4 gg = ((const float4*)g)[tid];
    float4 bb = ((const float4*)beta)[tid];
    __half2 h0 = __floats2half2_rn((v.x - mean) * rstd * gg.x + bb.x,
                                   (v.y - mean) * rstd * gg.y + bb.y);
    __half2 h1 = __floats2half2_rn((v.z - mean) * rstd * gg.z + bb.z,
                                   (v.w - mean) * rstd * gg.w + bb.w);
    uint2 pk;
    pk.x = *(uint32_t*)&h0;
    pk.y = *(uint32_t*)&h1;
    *(uint2*)&out[(size_t)row * Dv + 4 * tid] = pk;
}

// ---------------------------------------------------------------------------
// fp16 tensor-core flash attention, banded (causal + 10 lookahead).
// CTA = 128 queries x 1 head. 8 warps x 16 query rows. Key tiles of 64.
// Smem (halfs, pad 72): Qs[128][72] Ks[64][72] Vs[64][72] Ps[128][72].
// ---------------------------------------------------------------------------
#define APADH 72
#define AQ_OFF 0
#define AK_OFF (128 * APADH)
#define AV_OFF (AK_OFF + 64 * APADH)
#define AP_OFF (AV_OFF + 64 * APADH)
#define ASMEM_HALFS (AP_OFF + 128 * APADH)   // 27648 halfs = 55296 B

__global__ __launch_bounds__(256, 2) void attn_tc_kernel(
    const __half* __restrict__ qkv, const __half* __restrict__ vt, __half* __restrict__ o)
{
    extern __shared__ __half smh[];
    __half* Qs = smh + AQ_OFF;
    __half* Ks = smh + AK_OFF;
    __half* Vs = smh + AV_OFF;
    __half* Ps = smh + AP_OFF;

    int tid  = threadIdx.x;
    int lane = tid & 31;
    int wq   = tid >> 5;
    int lr   = lane >> 2;
    int lc   = lane & 3;
    int qt   = 15 - blockIdx.x;
    int q0   = qt * 128;
    int h    = blockIdx.y;
    int b    = blockIdx.z;

    const float SCALE = 0.125f * 1.4426950408889634f;
    const __half2 s2 = __floats2half2_rn(SCALE, SCALE);

    // Load + scale Q tile (128 rows x 64 halfs, 16B chunks)
    for (int i = tid; i < 128 * 8; i += 256) {
        int row = i >> 3;
        int c8  = (i & 7) << 3;
        uint4 v = *(const uint4*)&qkv[(size_t)(b * Tv + q0 + row) * 3072 + h * 64 + c8];
        __half2* p = (__half2*)&v;
        p[0] = __hmul2(p[0], s2); p[1] = __hmul2(p[1], s2);
        p[2] = __hmul2(p[2], s2); p[3] = __hmul2(p[3], s2);
        *(uint4*)&Qs[row * APADH + c8] = v;
    }

    int r0  = wq * 16 + lr;
    int iq0 = q0 + r0;
    int iq1 = iq0 + 8;
    int lim0 = iq0 + WINDOWv;
    int lim1 = iq1 + WINDOWv;

    float m0 = -1e30f, m1 = -1e30f, l0 = 0.f, l1 = 0.f;
    float oacc[8][4];
    #pragma unroll
    for (int nf = 0; nf < 8; nf++)
        #pragma unroll
        for (int e = 0; e < 4; e++) oacc[nf][e] = 0.f;

    int kmax   = min(q0 + 128 + WINDOWv, Tv);
    int ntiles = (kmax + 63) >> 6;

    const __half* vbase = vt + (size_t)((b * Hv + h) * 64) * Tv;

    for (int kt = 0; kt < ntiles; kt++) {
        int k0 = kt << 6;
        __syncthreads();
        // Copy K tile [j][d] and V^T tile [d][j] (pure 16B copies)
        for (int i = tid; i < 64 * 8; i += 256) {
            int row = i >> 3;
            int c8  = (i & 7) << 3;
            *(uint4*)&Ks[row * APADH + c8] =
                *(const uint4*)&qkv[(size_t)(b * Tv + k0 + row) * 3072 + 1024 + h * 64 + c8];
            *(uint4*)&Vs[row * APADH + c8] =
                *(const uint4*)&vbase[(size_t)row * Tv + k0 + c8];
        }
        __syncthreads();

        // S = Q K^T
        float sacc[8][4];
        #pragma unroll
        for (int jf = 0; jf < 8; jf++)
            #pragma unroll
            for (int e = 0; e < 4; e++) sacc[jf][e] = 0.f;

        #pragma unroll
        for (int kd = 0; kd < 64; kd += 16) {
            uint32_t a[4], bfr[8][2];
            const __half* ap = Qs + r0 * APADH + kd + 2 * lc;
            a[0] = *(const uint32_t*)&ap[0];
            a[1] = *(const uint32_t*)&ap[8 * APADH];
            a[2] = *(const uint32_t*)&ap[8];
            a[3] = *(const uint32_t*)&ap[8 * APADH + 8];
            #pragma unroll
            for (int jf = 0; jf < 8; jf++) {
                const __half* bp = Ks + (jf * 8 + lr) * APADH + kd + 2 * lc;
                bfr[jf][0] = *(const uint32_t*)&bp[0];
                bfr[jf][1] = *(const uint32_t*)&bp[8];
            }
            #pragma unroll
            for (int jf = 0; jf < 8; jf++)
                mma_f16(sacc[jf], a, bfr[jf]);
        }

        // Mask + row max (rows r0, r0+8)
        int jbase = k0 + 2 * lc;
        float mx0 = -1e30f, mx1 = -1e30f;
        #pragma unroll
        for (int jf = 0; jf < 8; jf++) {
            int jA = jbase + jf * 8, jB = jA + 1;
            sacc[jf][0] = (jA <= lim0) ? sacc[jf][0] : -1e30f;
            sacc[jf][1] = (jB <= lim0) ? sacc[jf][1] : -1e30f;
            sacc[jf][2] = (jA <= lim1) ? sacc[jf][2] : -1e30f;
            sacc[jf][3] = (jB <= lim1) ? sacc[jf][3] : -1e30f;
            mx0 = fmaxf(mx0, fmaxf(sacc[jf][0], sacc[jf][1]));
            mx1 = fmaxf(mx1, fmaxf(sacc[jf][2], sacc[jf][3]));
        }
        mx0 = fmaxf(mx0, __shfl_xor_sync(0xffffffffu, mx0, 1));
        mx0 = fmaxf(mx0, __shfl_xor_sync(0xffffffffu, mx0, 2));
        mx1 = fmaxf(mx1, __shfl_xor_sync(0xffffffffu, mx1, 1));
        mx1 = fmaxf(mx1, __shfl_xor_sync(0xffffffffu, mx1, 2));

        float mn0 = fmaxf(m0, mx0), mn1 = fmaxf(m1, mx1);
        float corr0 = exp2f(m0 - mn0), corr1 = exp2f(m1 - mn1);

        float ps0 = 0.f, ps1 = 0.f;
        #pragma unroll
        for (int jf = 0; jf < 8; jf++) {
            float p00 = exp2f(sacc[jf][0] - mn0);
            float p01 = exp2f(sacc[jf][1] - mn0);
            float p10 = exp2f(sacc[jf][2] - mn1);
            float p11 = exp2f(sacc[jf][3] - mn1);
            ps0 += p00 + p01;
            ps1 += p10 + p11;
            *(__half2*)&Ps[r0 * APADH + jf * 8 + 2 * lc]       = __floats2half2_rn(p00, p01);
            *(__half2*)&Ps[(r0 + 8) * APADH + jf * 8 + 2 * lc] = __floats2half2_rn(p10, p11);
        }
        ps0 += __shfl_xor_sync(0xffffffffu, ps0, 1);
        ps0 += __shfl_xor_sync(0xffffffffu, ps0, 2);
        ps1 += __shfl_xor_sync(0xffffffffu, ps1, 1);
        ps1 += __shfl_xor_sync(0xffffffffu, ps1, 2);

        l0 = l0 * corr0 + ps0;
        l1 = l1 * corr1 + ps1;
        m0 = mn0; m1 = mn1;
        #pragma unroll
        for (int nf = 0; nf < 8; nf++) {
            oacc[nf][0] *= corr0; oacc[nf][1] *= corr0;
            oacc[nf][2] *= corr1; oacc[nf][3] *= corr1;
        }
        __syncwarp();

        // O += P V   (A = P from smem, B = V^T tile)
        #pragma unroll
        for (int kj = 0; kj < 64; kj += 16) {
            uint32_t a[4], bfr[8][2];
            const __half* ap = Ps + r0 * APADH + kj + 2 * lc;
            a[0] = *(const uint32_t*)&ap[0];
            a[1] = *(const uint32_t*)&ap[8 * APADH];
            a[2] = *(const uint32_t*)&ap[8];
            a[3] = *(const uint32_t*)&ap[8 * APADH + 8];
            #pragma unroll
            for (int nf = 0; nf < 8; nf++) {
                const __half* bp = Vs + (nf * 8 + lr) * APADH + kj + 2 * lc;
                bfr[nf][0] = *(const uint32_t*)&bp[0];
                bfr[nf][1] = *(const uint32_t*)&bp[8];
            }
            #pragma unroll
            for (int nf = 0; nf < 8; nf++)
                mma_f16(oacc[nf], a, bfr[nf]);
        }
        __syncwarp();
    }

    // Normalize and store (fp16; feeds out-proj GEMM)
    float inv0 = 1.0f / l0, inv1 = 1.0f / l1;
    #pragma unroll
    for (int nf = 0; nf < 8; nf++) {
        int col = h * 64 + nf * 8 + 2 * lc;
        *(__half2*)&o[(size_t)(b * Tv + iq0) * Dv + col] =
            __floats2half2_rn(oacc[nf][0] * inv0, oacc[nf][1] * inv0);
        *(__half2*)&o[(size_t)(b * Tv + iq1) * Dv + col] =
            __floats2half2_rn(oacc[nf][2] * inv1, oacc[nf][3] * inv1);
    }
}

// ---------------------------------------------------------------------------
// Launch
// ---------------------------------------------------------------------------
extern "C" void kernel_launch(void* const* d_in, const int* in_sizes, int n_in,
                              void* d_out, int out_size)
{
    const float* x     = (const float*)d_in[0];
    const float* in_w  = (const float*)d_in[1];
    const float* in_b  = (const float*)d_in[2];
    const float* out_w = (const float*)d_in[3];
    const float* out_b = (const float*)d_in[4];
    const float* ln1g  = (const float*)d_in[5];
    const float* ln1b  = (const float*)d_in[6];
    const float* w1    = (const float*)d_in[7];
    const float* b1    = (const float*)d_in[8];
    const float* w2    = (const float*)d_in[9];
    const float* b2    = (const float*)d_in[10];
    const float* ln2g  = (const float*)d_in[11];
    const float* ln2b  = (const float*)d_in[12];
    float* out = (float*)d_out;

    __half *h, *qkv, *o, *ff, *vt, *wqkv, *wout, *w1h, *w2h;
    cudaGetSymbolAddress((void**)&h,    g_h);
    cudaGetSymbolAddress((void**)&qkv,  g_qkv);
    cudaGetSymbolAddress((void**)&o,    g_o);
    cudaGetSymbolAddress((void**)&ff,   g_ff);
    cudaGetSymbolAddress((void**)&vt,   g_vt);
    cudaGetSymbolAddress((void**)&wqkv, g_wqkv);
    cudaGetSymbolAddress((void**)&wout, g_wout);
    cudaGetSymbolAddress((void**)&w1h,  g_w1h);
    cudaGetSymbolAddress((void**)&w2h,  g_w2h);

    const int SMEM_GEMM = SMEM_HALFS * 2;    // 81920 B
    const int SMEM_ATTN = ASMEM_HALFS * 2;   // 55296 B
    cudaFuncSetAttribute(attn_tc_kernel, cudaFuncAttributeMaxDynamicSharedMemorySize, SMEM_ATTN);
    cudaFuncSetAttribute(tc_gemm<0>, cudaFuncAttributeMaxDynamicSharedMemorySize, SMEM_GEMM);
    cudaFuncSetAttribute(tc_gemm<1>, cudaFuncAttributeMaxDynamicSharedMemorySize, SMEM_GEMM);
    cudaFuncSetAttribute(tc_gemm<2>, cudaFuncAttributeMaxDynamicSharedMemorySize, SMEM_GEMM);

    // 0) fp16-convert all weights (single fused launch)
    round_all_kernel<<<592, 256>>>((const float4*)in_w,  wqkv,
                                   (const float4*)out_w, wout,
                                   (const float4*)w1,    w1h,
                                   (const float4*)w2,    w2h);

    // 1) h = LN1(x)  (fp16)
    ln_kernel<<<Mv, 256>>>(x, ln1g, ln1b, h);

    // 2) qkv = h @ in_proj_w^T + in_proj_b     [4096, 3072] (fp16 out)
    tc_gemm<0><<<dim3(3072 / BN, Mv / BM), 256, SMEM_GEMM>>>(h, wqkv, in_b, nullptr, qkv, 3072, 1024);

    // 3a) V transpose: g_vt[b][h][d][t]
    vt_kernel<<<dim3(Tv / 32, Dv / 32, Bv), dim3(32, 8)>>>(qkv, vt);

    // 3b) o = fp16 tensor-core banded flash attention
    attn_tc_kernel<<<dim3(Tv / 128, Hv, Bv), 256, SMEM_ATTN>>>(qkv, vt, o);

    // 4) x1 = o @ out_w^T + out_b + x  -> d_out (fp32)
    tc_gemm<2><<<dim3(1024 / BN, Mv / BM), 256, SMEM_GEMM>>>(o, wout, out_b, x, out, 1024, 1024);

    // 5) h2 = LN2(x1)  (fp16)
    ln_kernel<<<Mv, 256>>>(out, ln2g, ln2b, h);

    // 6) ff = GELU(h2 @ w1^T + b1)             [4096, 4096] (fp16 out)
    tc_gemm<1><<<dim3(4096 / BN, Mv / BM), 256, SMEM_GEMM>>>(h, w1h, b1, nullptr, ff, 4096, 1024);

    // 7) out = ff @ w2^T + b2 + x1  (in-place residual on d_out, fp32)
    tc_gemm<2><<<dim3(1024 / BN, Mv / BM), 256, SMEM_GEMM>>>(ff, w2h, b2, out, out, 1024, 4096);
}